// round 10
// baseline (speedup 1.0000x reference)
#include <cuda_runtime.h>
#include <cstdint>
#include <float.h>

#define N_NODES 100000
#define N_EDGES 2000000
#define HID 32
#define NCLS 40
#define NODE_BLOCKS 3125   // 100000 / 32 nodes per block (8 warps x 4 nodes)

// ---------------- scratch (static device memory; no allocation) ----------------
__device__ float g_h1 [N_NODES * HID];
__device__ float g_m1 [N_NODES * HID];
__device__ float g_agg1[N_NODES * HID];
__device__ float g_h2 [N_NODES * NCLS];
__device__ float g_m2 [N_NODES * NCLS];
__device__ float g_agg2[N_NODES * NCLS];

// CSR build scratch
__device__ int   g_cnt[N_NODES];        // histogram, then cursor
__device__ int   g_off[N_NODES + 1];    // exclusive offsets
__device__ int   g_bsum[128];           // scan block sums (98 used)
__device__ int   g_ssrc[N_EDGES];       // dst-sorted src
__device__ float g_sw  [N_EDGES];       // dst-sorted weight

// ---------------- K1: h1 = x@W1p, m1 = h1@W1m (4 nodes/warp); zero g_cnt -------
__global__ void __launch_bounds__(256) k_proj1(const float* __restrict__ x,
                        const float* __restrict__ Wp,
                        const float* __restrict__ Wm) {
    __shared__ float sWp[1024];
    __shared__ float sWm[1024];
    int t = threadIdx.x;
    int gid = blockIdx.x * 256 + t;
    if (gid < N_NODES) g_cnt[gid] = 0;       // zero histogram for CSR build
    for (int i = t; i < 1024; i += 256) { sWp[i] = Wp[i]; sWm[i] = Wm[i]; }
    __syncthreads();

    int lane = t & 31;
    int n0 = blockIdx.x * 32 + (t >> 5) * 4;

    float xv[4], h[4], m[4];
#pragma unroll
    for (int i = 0; i < 4; i++) { xv[i] = x[(n0 + i) * 32 + lane]; h[i] = 0.f; m[i] = 0.f; }

#pragma unroll
    for (int k = 0; k < 32; k++) {
        float w = sWp[k * 32 + lane];
#pragma unroll
        for (int i = 0; i < 4; i++)
            h[i] = fmaf(__shfl_sync(0xffffffffu, xv[i], k), w, h[i]);
    }
#pragma unroll
    for (int k = 0; k < 32; k++) {
        float w = sWm[k * 32 + lane];
#pragma unroll
        for (int i = 0; i < 4; i++)
            m[i] = fmaf(__shfl_sync(0xffffffffu, h[i], k), w, m[i]);
    }
#pragma unroll
    for (int i = 0; i < 4; i++) {
        int idx = (n0 + i) * 32 + lane;
        g_h1[idx] = h[i];
        g_m1[idx] = m[i];
    }
}

// ---------------- CSR build: histogram / scan / scatter ----------------
__global__ void k_hist(const int* __restrict__ ei) {
    int e = blockIdx.x * 256 + threadIdx.x;
    if (e < N_EDGES) atomicAdd(&g_cnt[ei[N_EDGES + e]], 1);
}

__global__ void k_scan1() {   // 98 blocks x 1024: per-block exclusive scan
    __shared__ int s[1024];
    int tid = threadIdx.x;
    int i = blockIdx.x * 1024 + tid;
    int v = (i < N_NODES) ? g_cnt[i] : 0;
    s[tid] = v;
    __syncthreads();
#pragma unroll
    for (int d = 1; d < 1024; d <<= 1) {
        int t2 = (tid >= d) ? s[tid - d] : 0;
        __syncthreads();
        s[tid] += t2;
        __syncthreads();
    }
    if (i < N_NODES) g_off[i] = s[tid] - v;      // exclusive within block
    if (tid == 1023) g_bsum[blockIdx.x] = s[1023];
}

__global__ void k_scan2() {   // 1 block x 128: exclusive scan of 98 block sums
    __shared__ int s[128];
    int tid = threadIdx.x;
    int v = (tid < 98) ? g_bsum[tid] : 0;
    s[tid] = v;
    __syncthreads();
#pragma unroll
    for (int d = 1; d < 128; d <<= 1) {
        int t2 = (tid >= d) ? s[tid - d] : 0;
        __syncthreads();
        s[tid] += t2;
        __syncthreads();
    }
    if (tid < 98) g_bsum[tid] = s[tid] - v;      // exclusive
}

__global__ void k_scan3() {   // finalize offsets + init cursors
    int i = blockIdx.x * 256 + threadIdx.x;
    if (i < N_NODES) {
        int o = g_off[i] + g_bsum[i >> 10];
        g_off[i] = o;
        g_cnt[i] = o;                             // cursor
    }
    if (i == N_NODES) g_off[N_NODES] = N_EDGES;
}

__global__ void k_scatter(const int* __restrict__ ei,
                          const float* __restrict__ ew) {
    int e = blockIdx.x * 256 + threadIdx.x;
    if (e >= N_EDGES) return;
    int d = ei[N_EDGES + e];
    int p = atomicAdd(&g_cnt[d], 1);
    g_ssrc[p] = ei[e];
    g_sw[p]   = ew[e];
}

// ---------------- K2: gather layer 1 (warp per dst node, lane = col) ----------
__global__ void __launch_bounds__(256) k_gather1() {
    int t = threadIdx.x;
    int lane = t & 31;
    int node = blockIdx.x * 8 + (t >> 5);
    if (node >= N_NODES) return;
    int beg = g_off[node];
    int end = g_off[node + 1];
    float acc = 0.f;
    for (int base = beg; base < end; base += 32) {
        int n = end - base; if (n > 32) n = 32;
        int idx = base + lane;
        int   src = (lane < n) ? g_ssrc[idx] : 0;
        float wv  = (lane < n) ? g_sw[idx]   : 0.f;
#pragma unroll 4
        for (int j = 0; j < n; j++) {
            int   s  = __shfl_sync(0xffffffffu, src, j);
            float ww = __shfl_sync(0xffffffffu, wv,  j);
            acc = fmaf(g_m1[s * 32 + lane], ww, acc);
        }
    }
    g_agg1[node * 32 + lane] = acc;
}

// ------- K3: GRU1 + ReLU + proj2 + msg2 fused (4 nodes/warp) --------
__global__ void __launch_bounds__(256) k_gru1_proj2(
                             const float* __restrict__ wih,
                             const float* __restrict__ whh,
                             const float* __restrict__ bih,
                             const float* __restrict__ bhh,
                             const float* __restrict__ Wp,
                             const float* __restrict__ Wm) {
    __shared__ float sWi[32 * 97]; // transposed [k][r], padded
    __shared__ float sWh[32 * 97];
    __shared__ float sWp[32 * 40];
    __shared__ float sWm[40 * 40];
    int t = threadIdx.x;
    for (int i = t; i < 96 * 32; i += 256) {
        int r = i >> 5, k = i & 31;
        sWi[k * 97 + r] = wih[i];
        sWh[k * 97 + r] = whh[i];
    }
    for (int i = t; i < 32 * 40; i += 256) sWp[i] = Wp[i];
    for (int i = t; i < 40 * 40; i += 256) sWm[i] = Wm[i];
    __syncthreads();

    int lane = t & 31;
    int n0 = blockIdx.x * 32 + (t >> 5) * 4;

    float a[4], hv[4];
    float gir[4], giz[4], gin[4], ghr[4], ghz[4], ghn[4];
    float b_ir = bih[lane], b_iz = bih[32 + lane], b_in = bih[64 + lane];
    float b_hr = bhh[lane], b_hz = bhh[32 + lane], b_hn = bhh[64 + lane];
#pragma unroll
    for (int i = 0; i < 4; i++) {
        int idx = (n0 + i) * 32 + lane;
        a[i] = g_agg1[idx];
        hv[i] = g_h1[idx];
        gir[i] = b_ir; giz[i] = b_iz; gin[i] = b_in;
        ghr[i] = b_hr; ghz[i] = b_hz; ghn[i] = b_hn;
    }

#pragma unroll 8
    for (int k = 0; k < 32; k++) {
        const float* wi = &sWi[k * 97];
        const float* wh = &sWh[k * 97];
        float wir = wi[lane], wiz = wi[32 + lane], win = wi[64 + lane];
        float whr = wh[lane], whz = wh[32 + lane], whn = wh[64 + lane];
#pragma unroll
        for (int i = 0; i < 4; i++) {
            float ak = __shfl_sync(0xffffffffu, a[i],  k);
            float hk = __shfl_sync(0xffffffffu, hv[i], k);
            gir[i] = fmaf(ak, wir, gir[i]);
            giz[i] = fmaf(ak, wiz, giz[i]);
            gin[i] = fmaf(ak, win, gin[i]);
            ghr[i] = fmaf(hk, whr, ghr[i]);
            ghz[i] = fmaf(hk, whz, ghz[i]);
            ghn[i] = fmaf(hk, whn, ghn[i]);
        }
    }

    float hr[4];
#pragma unroll
    for (int i = 0; i < 4; i++) {
        float r = 1.f / (1.f + __expf(-(gir[i] + ghr[i])));
        float z = 1.f / (1.f + __expf(-(giz[i] + ghz[i])));
        float n = tanhf(gin[i] + r * ghn[i]);
        hr[i] = fmaxf((1.f - z) * n + z * hv[i], 0.f);
    }

    // ---- proj2: h2 = hr@Wp (32->40), m2 = h2@Wm (40->40) ----
    int c2 = 32 + (lane & 7);
    float h_lo[4] = {0,0,0,0}, h_hi[4] = {0,0,0,0};
#pragma unroll 8
    for (int k = 0; k < 32; k++) {
        float wlo = sWp[k * 40 + lane];
        float whi = sWp[k * 40 + c2];
#pragma unroll
        for (int i = 0; i < 4; i++) {
            float ak = __shfl_sync(0xffffffffu, hr[i], k);
            h_lo[i] = fmaf(ak, wlo, h_lo[i]);
            h_hi[i] = fmaf(ak, whi, h_hi[i]);
        }
    }
    float m_lo[4] = {0,0,0,0}, m_hi[4] = {0,0,0,0};
#pragma unroll 8
    for (int k = 0; k < 32; k++) {
        float wlo = sWm[k * 40 + lane];
        float whi = sWm[k * 40 + c2];
#pragma unroll
        for (int i = 0; i < 4; i++) {
            float hk = __shfl_sync(0xffffffffu, h_lo[i], k);
            m_lo[i] = fmaf(hk, wlo, m_lo[i]);
            m_hi[i] = fmaf(hk, whi, m_hi[i]);
        }
    }
#pragma unroll
    for (int k = 0; k < 8; k++) {
        float wlo = sWm[(32 + k) * 40 + lane];
        float whi = sWm[(32 + k) * 40 + c2];
#pragma unroll
        for (int i = 0; i < 4; i++) {
            float hk = __shfl_sync(0xffffffffu, h_hi[i], k);
            m_lo[i] = fmaf(hk, wlo, m_lo[i]);
            m_hi[i] = fmaf(hk, whi, m_hi[i]);
        }
    }
#pragma unroll
    for (int i = 0; i < 4; i++) {
        int base = (n0 + i) * 40;
        g_h2[base + lane] = h_lo[i];
        g_m2[base + lane] = m_lo[i];
        if (lane < 8) {
            g_h2[base + 32 + lane] = h_hi[i];
            g_m2[base + 32 + lane] = m_hi[i];
        }
    }
}

// ---------------- K4: gather layer 2 (warp per dst node, 40 cols) ----------
__global__ void __launch_bounds__(256) k_gather2() {
    int t = threadIdx.x;
    int lane = t & 31;
    int node = blockIdx.x * 8 + (t >> 5);
    if (node >= N_NODES) return;
    int beg = g_off[node];
    int end = g_off[node + 1];
    float acc = 0.f, acc2 = 0.f;
    for (int base = beg; base < end; base += 32) {
        int n = end - base; if (n > 32) n = 32;
        int idx = base + lane;
        int   src = (lane < n) ? g_ssrc[idx] : 0;
        float wv  = (lane < n) ? g_sw[idx]   : 0.f;
#pragma unroll 4
        for (int j = 0; j < n; j++) {
            int   s  = __shfl_sync(0xffffffffu, src, j);
            float ww = __shfl_sync(0xffffffffu, wv,  j);
            const float* row = &g_m2[s * 40];
            acc = fmaf(row[lane], ww, acc);
            if (lane < 8) acc2 = fmaf(row[32 + lane], ww, acc2);
        }
    }
    g_agg2[node * 40 + lane] = acc;
    if (lane < 8) g_agg2[node * 40 + 32 + lane] = acc2;
}

// -------- K5: GRU2 + log_softmax (4 nodes/warp, exact-fit hi pass) ----------
__global__ void __launch_bounds__(256) k_gru2(float* __restrict__ out,
                       const float* __restrict__ wih,
                       const float* __restrict__ whh,
                       const float* __restrict__ bih,
                       const float* __restrict__ bhh) {
    extern __shared__ float dyn[];
    float* sWi = dyn;                  // 40*121  [k][row], padded
    float* sWh = sWi + 40 * 121;       // 40*121
    float* sStage = sWh + 40 * 121;    // 8 warps * 2 * 164

    int t = threadIdx.x;
    for (int i = t; i < 120 * 40; i += 256) {
        int r = i / 40, k = i % 40;
        sWi[k * 121 + r] = wih[i];
        sWh[k * 121 + r] = whh[i];
    }
    __syncthreads();

    int lane = t & 31;
    int warp = t >> 5;
    int n0 = blockIdx.x * 32 + warp * 4;
    float* sA = sStage + warp * 328;
    float* sH = sA + 164;

    float a_lo[4], h_lo[4], a_hi[4], h_hi[4];
#pragma unroll
    for (int i = 0; i < 4; i++) {
        int b = (n0 + i) * 40;
        float av = g_agg2[b + lane];
        float hvv = g_h2[b + lane];
        a_lo[i] = av; h_lo[i] = hvv;
        sA[i * 41 + lane] = av;
        sH[i * 41 + lane] = hvv;
        if (lane < 8) {
            float avh = g_agg2[b + 32 + lane];
            float hvh = g_h2[b + 32 + lane];
            a_hi[i] = avh; h_hi[i] = hvh;
            sA[i * 41 + 32 + lane] = avh;
            sH[i * 41 + 32 + lane] = hvh;
        } else { a_hi[i] = 0.f; h_hi[i] = 0.f; }
    }
    __syncwarp();

    float gir[4], giz[4], gin[4], ghr[4], ghz[4], ghn[4];
    {
        float b0 = bih[lane], b1 = bih[40 + lane], b2 = bih[80 + lane];
        float b3 = bhh[lane], b4 = bhh[40 + lane], b5 = bhh[80 + lane];
#pragma unroll
        for (int i = 0; i < 4; i++) {
            gir[i] = b0; giz[i] = b1; gin[i] = b2;
            ghr[i] = b3; ghz[i] = b4; ghn[i] = b5;
        }
    }
    int hi_node = lane >> 3;
    int hi_col  = 32 + (lane & 7);
    float Gir = bih[hi_col], Giz = bih[40 + hi_col], Gin = bih[80 + hi_col];
    float Ghr = bhh[hi_col], Ghz = bhh[40 + hi_col], Ghn = bhh[80 + hi_col];
    const float* aN = sA + hi_node * 41;
    const float* hN = sH + hi_node * 41;

#pragma unroll 4
    for (int k = 0; k < 32; k++) {
        const float* wi = &sWi[k * 121];
        const float* wh = &sWh[k * 121];
        float wi0 = wi[lane], wi1 = wi[40 + lane], wi2 = wi[80 + lane];
        float wh0 = wh[lane], wh1 = wh[40 + lane], wh2 = wh[80 + lane];
        {
            float ak = aN[k], hk = hN[k];
            Gir = fmaf(ak, wi[hi_col],      Gir);
            Giz = fmaf(ak, wi[40 + hi_col], Giz);
            Gin = fmaf(ak, wi[80 + hi_col], Gin);
            Ghr = fmaf(hk, wh[hi_col],      Ghr);
            Ghz = fmaf(hk, wh[40 + hi_col], Ghz);
            Ghn = fmaf(hk, wh[80 + hi_col], Ghn);
        }
#pragma unroll
        for (int i = 0; i < 4; i++) {
            float ak = __shfl_sync(0xffffffffu, a_lo[i], k);
            float hk = __shfl_sync(0xffffffffu, h_lo[i], k);
            gir[i] = fmaf(ak, wi0, gir[i]);
            giz[i] = fmaf(ak, wi1, giz[i]);
            gin[i] = fmaf(ak, wi2, gin[i]);
            ghr[i] = fmaf(hk, wh0, ghr[i]);
            ghz[i] = fmaf(hk, wh1, ghz[i]);
            ghn[i] = fmaf(hk, wh2, ghn[i]);
        }
    }
#pragma unroll
    for (int k = 32; k < 40; k++) {
        const float* wi = &sWi[k * 121];
        const float* wh = &sWh[k * 121];
        float wi0 = wi[lane], wi1 = wi[40 + lane], wi2 = wi[80 + lane];
        float wh0 = wh[lane], wh1 = wh[40 + lane], wh2 = wh[80 + lane];
        {
            float ak = aN[k], hk = hN[k];
            Gir = fmaf(ak, wi[hi_col],      Gir);
            Giz = fmaf(ak, wi[40 + hi_col], Giz);
            Gin = fmaf(ak, wi[80 + hi_col], Gin);
            Ghr = fmaf(hk, wh[hi_col],      Ghr);
            Ghz = fmaf(hk, wh[40 + hi_col], Ghz);
            Ghn = fmaf(hk, wh[80 + hi_col], Ghn);
        }
#pragma unroll
        for (int i = 0; i < 4; i++) {
            float ak = __shfl_sync(0xffffffffu, a_hi[i], k - 32);
            float hk = __shfl_sync(0xffffffffu, h_hi[i], k - 32);
            gir[i] = fmaf(ak, wi0, gir[i]);
            giz[i] = fmaf(ak, wi1, giz[i]);
            gin[i] = fmaf(ak, wi2, gin[i]);
            ghr[i] = fmaf(hk, wh0, ghr[i]);
            ghz[i] = fmaf(hk, wh1, ghz[i]);
            ghn[i] = fmaf(hk, wh2, ghn[i]);
        }
    }

    float v1[4];
#pragma unroll
    for (int i = 0; i < 4; i++) {
        float r1 = 1.f / (1.f + __expf(-(gir[i] + ghr[i])));
        float z1 = 1.f / (1.f + __expf(-(giz[i] + ghz[i])));
        float n1 = tanhf(gin[i] + r1 * ghn[i]);
        v1[i] = (1.f - z1) * n1 + z1 * h_lo[i];
    }
    float v2;
    {
        float hvh = sH[hi_node * 41 + hi_col];
        float r2 = 1.f / (1.f + __expf(-(Gir + Ghr)));
        float z2 = 1.f / (1.f + __expf(-(Giz + Ghz)));
        float n2 = tanhf(Gin + r2 * Ghn);
        v2 = (1.f - z2) * n2 + z2 * hvh;
    }

    __syncwarp();
#pragma unroll
    for (int i = 0; i < 4; i++) sA[i * 41 + lane] = v1[i];
    sA[hi_node * 41 + hi_col] = v2;
    __syncwarp();

#pragma unroll
    for (int i = 0; i < 4; i++) {
        float x1 = sA[i * 41 + lane];
        float x2 = (lane < 8) ? sA[i * 41 + 32 + lane] : -FLT_MAX;
        float vmax = fmaxf(x1, x2);
#pragma unroll
        for (int o = 16; o > 0; o >>= 1)
            vmax = fmaxf(vmax, __shfl_xor_sync(0xffffffffu, vmax, o));
        float se = __expf(x1 - vmax) + ((lane < 8) ? __expf(x2 - vmax) : 0.f);
#pragma unroll
        for (int o = 16; o > 0; o >>= 1)
            se += __shfl_xor_sync(0xffffffffu, se, o);
        float ls = vmax + logf(se);

        int b = (n0 + i) * 40;
        out[b + lane] = x1 - ls;
        if (lane < 8) out[b + 32 + lane] = x2 - ls;
    }
}

// ---------------- launch ----------------
extern "C" void kernel_launch(void* const* d_in, const int* in_sizes, int n_in,
                              void* d_out, int out_size) {
    const float* x   = (const float*)d_in[0];
    const int*   ei  = (const int*)d_in[1];     // int32 (JAX x64 disabled)
    const float* ew  = (const float*)d_in[2];
    const float* W1p = (const float*)d_in[3];
    const float* W1m = (const float*)d_in[4];
    const float* g1wih = (const float*)d_in[5];
    const float* g1whh = (const float*)d_in[6];
    const float* g1bih = (const float*)d_in[7];
    const float* g1bhh = (const float*)d_in[8];
    const float* W2p = (const float*)d_in[9];
    const float* W2m = (const float*)d_in[10];
    const float* g2wih = (const float*)d_in[11];
    const float* g2whh = (const float*)d_in[12];
    const float* g2bih = (const float*)d_in[13];
    const float* g2bhh = (const float*)d_in[14];
    float* out = (float*)d_out;

    const int smem2 = (40 * 121 * 2 + 8 * 328) * 4;   // 49216 B
    cudaFuncSetAttribute(k_gru2, cudaFuncAttributeMaxDynamicSharedMemorySize, smem2);

    const int EB = (N_EDGES + 255) / 256;       // 7813

    k_proj1<<<NODE_BLOCKS, 256>>>(x, W1p, W1m); // also zeroes g_cnt

    // CSR build
    k_hist<<<EB, 256>>>(ei);
    k_scan1<<<98, 1024>>>();
    k_scan2<<<1, 128>>>();
    k_scan3<<<(N_NODES + 256) / 256, 256>>>();
    k_scatter<<<EB, 256>>>(ei, ew);

    k_gather1<<<(N_NODES + 7) / 8, 256>>>();

    k_gru1_proj2<<<NODE_BLOCKS, 256>>>(g1wih, g1whh, g1bih, g1bhh, W2p, W2m);

    k_gather2<<<(N_NODES + 7) / 8, 256>>>();

    k_gru2<<<NODE_BLOCKS, 256, smem2>>>(out, g2wih, g2whh, g2bih, g2bhh);
}

// round 11
// speedup vs baseline: 1.0475x; 1.0475x over previous
#include <cuda_runtime.h>
#include <cstdint>
#include <float.h>

#define N_NODES 100000
#define N_EDGES 2000000
#define HID 32
#define NCLS 40
#define NB128 3125    // blocks of 128 threads, 4 warps x 8 nodes = 32 nodes/block
#define NB256 3125    // blocks of 256 threads, 8 warps x 4 nodes = 32 nodes/block

// ---------------- scratch (static device memory; no allocation) ----------------
__device__ float g_h1 [N_NODES * HID];
__device__ float g_m1 [N_NODES * HID];
__device__ float g_agg1[N_NODES * HID];
__device__ float g_h2 [N_NODES * NCLS];
__device__ float g_m2 [N_NODES * NCLS];
__device__ float g_agg2[N_NODES * NCLS];

__device__ __forceinline__ void red_add_v4(float* addr, float4 v) {
    asm volatile("red.global.add.v4.f32 [%0], {%1,%2,%3,%4};"
                 :: "l"(addr), "f"(v.x), "f"(v.y), "f"(v.z), "f"(v.w)
                 : "memory");
}

// ---------------- K1: h1 = x@W1p, m1 = h1@W1m, zero agg1 (8 nodes/warp) --------
__global__ void __launch_bounds__(128) k_proj1(const float* __restrict__ x,
                        const float* __restrict__ Wp,
                        const float* __restrict__ Wm) {
    __shared__ float sWp[1024];
    __shared__ float sWm[1024];
    int t = threadIdx.x;
    for (int i = t; i < 1024; i += 128) { sWp[i] = Wp[i]; sWm[i] = Wm[i]; }
    __syncthreads();

    int lane = t & 31;
    int n0 = blockIdx.x * 32 + (t >> 5) * 8;

    float xv[8], h[8], m[8];
#pragma unroll
    for (int i = 0; i < 8; i++) { xv[i] = x[(n0 + i) * 32 + lane]; h[i] = 0.f; m[i] = 0.f; }

#pragma unroll 8
    for (int k = 0; k < 32; k++) {
        float w = sWp[k * 32 + lane];
#pragma unroll
        for (int i = 0; i < 8; i++)
            h[i] = fmaf(__shfl_sync(0xffffffffu, xv[i], k), w, h[i]);
    }
#pragma unroll 8
    for (int k = 0; k < 32; k++) {
        float w = sWm[k * 32 + lane];
#pragma unroll
        for (int i = 0; i < 8; i++)
            m[i] = fmaf(__shfl_sync(0xffffffffu, h[i], k), w, m[i]);
    }
#pragma unroll
    for (int i = 0; i < 8; i++) {
        int idx = (n0 + i) * 32 + lane;
        g_h1[idx] = h[i];
        g_m1[idx] = m[i];
        g_agg1[idx] = 0.f;
    }
}

// ---------------- K2: edge scatter layer 1 — 8 threads/edge, float4 + red.v4 ----
__global__ void k_edge1(const int* __restrict__ ei,
                        const float* __restrict__ ew) {
    long long tid = (long long)blockIdx.x * blockDim.x + threadIdx.x;
    int e = (int)(tid >> 3);
    if (e >= N_EDGES) return;
    int q = (int)(tid & 7);
    int src = ei[e];
    int dst = ei[N_EDGES + e];
    float w = ew[e];
    const float4* mrow = (const float4*)&g_m1[src * 32];
    float4 m = mrow[q];
    m.x *= w; m.y *= w; m.z *= w; m.w *= w;
    red_add_v4(&g_agg1[dst * 32 + q * 4], m);
}

// ------- K3: GRU1 + ReLU + proj2 + msg2 fused, zero agg2 (8 nodes/warp) --------
__global__ void __launch_bounds__(128) k_gru1_proj2(
                             const float* __restrict__ wih,
                             const float* __restrict__ whh,
                             const float* __restrict__ bih,
                             const float* __restrict__ bhh,
                             const float* __restrict__ Wp,
                             const float* __restrict__ Wm) {
    __shared__ float sWi[32 * 97]; // transposed [k][r], padded
    __shared__ float sWh[32 * 97];
    __shared__ float sWp[32 * 40];
    __shared__ float sWm[40 * 40];
    int t = threadIdx.x;
    for (int i = t; i < 96 * 32; i += 128) {
        int r = i >> 5, k = i & 31;
        sWi[k * 97 + r] = wih[i];
        sWh[k * 97 + r] = whh[i];
    }
    for (int i = t; i < 32 * 40; i += 128) sWp[i] = Wp[i];
    for (int i = t; i < 40 * 40; i += 128) sWm[i] = Wm[i];
    __syncthreads();

    int lane = t & 31;
    int n0 = blockIdx.x * 32 + (t >> 5) * 8;

    float a[8], hv[8];
    float gir[8], giz[8], gin[8], ghr[8], ghz[8], ghn[8];
    {
        float b_ir = bih[lane], b_iz = bih[32 + lane], b_in = bih[64 + lane];
        float b_hr = bhh[lane], b_hz = bhh[32 + lane], b_hn = bhh[64 + lane];
#pragma unroll
        for (int i = 0; i < 8; i++) {
            int idx = (n0 + i) * 32 + lane;
            a[i] = g_agg1[idx];
            hv[i] = g_h1[idx];
            gir[i] = b_ir; giz[i] = b_iz; gin[i] = b_in;
            ghr[i] = b_hr; ghz[i] = b_hz; ghn[i] = b_hn;
        }
    }

#pragma unroll 4
    for (int k = 0; k < 32; k++) {
        const float* wi = &sWi[k * 97];
        const float* wh = &sWh[k * 97];
        float wir = wi[lane], wiz = wi[32 + lane], win = wi[64 + lane];
        float whr = wh[lane], whz = wh[32 + lane], whn = wh[64 + lane];
#pragma unroll
        for (int i = 0; i < 8; i++) {
            float ak = __shfl_sync(0xffffffffu, a[i],  k);
            float hk = __shfl_sync(0xffffffffu, hv[i], k);
            gir[i] = fmaf(ak, wir, gir[i]);
            giz[i] = fmaf(ak, wiz, giz[i]);
            gin[i] = fmaf(ak, win, gin[i]);
            ghr[i] = fmaf(hk, whr, ghr[i]);
            ghz[i] = fmaf(hk, whz, ghz[i]);
            ghn[i] = fmaf(hk, whn, ghn[i]);
        }
    }

    float hr[8];
#pragma unroll
    for (int i = 0; i < 8; i++) {
        float r = 1.f / (1.f + __expf(-(gir[i] + ghr[i])));
        float z = 1.f / (1.f + __expf(-(giz[i] + ghz[i])));
        float n = tanhf(gin[i] + r * ghn[i]);
        hr[i] = fmaxf((1.f - z) * n + z * hv[i], 0.f);
    }

    // ---- proj2: h2 = hr@Wp (32->40), m2 = h2@Wm (40->40) ----
    int c2 = 32 + (lane & 7);
    float h_lo[8], h_hi[8];
#pragma unroll
    for (int i = 0; i < 8; i++) { h_lo[i] = 0.f; h_hi[i] = 0.f; }
#pragma unroll 4
    for (int k = 0; k < 32; k++) {
        float wlo = sWp[k * 40 + lane];
        float whi = sWp[k * 40 + c2];
#pragma unroll
        for (int i = 0; i < 8; i++) {
            float ak = __shfl_sync(0xffffffffu, hr[i], k);
            h_lo[i] = fmaf(ak, wlo, h_lo[i]);
            h_hi[i] = fmaf(ak, whi, h_hi[i]);
        }
    }
    float m_lo[8], m_hi[8];
#pragma unroll
    for (int i = 0; i < 8; i++) { m_lo[i] = 0.f; m_hi[i] = 0.f; }
#pragma unroll 4
    for (int k = 0; k < 32; k++) {
        float wlo = sWm[k * 40 + lane];
        float whi = sWm[k * 40 + c2];
#pragma unroll
        for (int i = 0; i < 8; i++) {
            float hk = __shfl_sync(0xffffffffu, h_lo[i], k);
            m_lo[i] = fmaf(hk, wlo, m_lo[i]);
            m_hi[i] = fmaf(hk, whi, m_hi[i]);
        }
    }
#pragma unroll
    for (int k = 0; k < 8; k++) {
        float wlo = sWm[(32 + k) * 40 + lane];
        float whi = sWm[(32 + k) * 40 + c2];
#pragma unroll
        for (int i = 0; i < 8; i++) {
            float hk = __shfl_sync(0xffffffffu, h_hi[i], k);
            m_lo[i] = fmaf(hk, wlo, m_lo[i]);
            m_hi[i] = fmaf(hk, whi, m_hi[i]);
        }
    }
#pragma unroll
    for (int i = 0; i < 8; i++) {
        int base = (n0 + i) * 40;
        g_h2[base + lane] = h_lo[i];
        g_m2[base + lane] = m_lo[i];
        g_agg2[base + lane] = 0.f;
        if (lane < 8) {
            g_h2[base + 32 + lane] = h_hi[i];
            g_m2[base + 32 + lane] = m_hi[i];
            g_agg2[base + 32 + lane] = 0.f;
        }
    }
}

// ---------------- K4: edge scatter layer 2 — 10 threads/edge, float4 + red.v4 ----
__global__ void k_edge2(const int* __restrict__ ei,
                        const float* __restrict__ ew) {
    long long tid = (long long)blockIdx.x * blockDim.x + threadIdx.x;
    int e = (int)(tid / 10);
    if (e >= N_EDGES) return;
    int q = (int)(tid - (long long)e * 10);
    int src = ei[e];
    int dst = ei[N_EDGES + e];
    float w = ew[e];
    const float4* mrow = (const float4*)&g_m2[src * 40];
    float4 m = mrow[q];
    m.x *= w; m.y *= w; m.z *= w; m.w *= w;
    red_add_v4(&g_agg2[dst * 40 + q * 4], m);
}

// -------- K5: GRU2 + log_softmax (4 nodes/warp, exact-fit hi pass) ----------
__global__ void __launch_bounds__(256) k_gru2(float* __restrict__ out,
                       const float* __restrict__ wih,
                       const float* __restrict__ whh,
                       const float* __restrict__ bih,
                       const float* __restrict__ bhh) {
    extern __shared__ float dyn[];
    float* sWi = dyn;                  // 40*121  [k][row], padded
    float* sWh = sWi + 40 * 121;       // 40*121
    float* sStage = sWh + 40 * 121;    // 8 warps * 2 * 164

    int t = threadIdx.x;
    for (int i = t; i < 120 * 40; i += 256) {
        int r = i / 40, k = i % 40;
        sWi[k * 121 + r] = wih[i];
        sWh[k * 121 + r] = whh[i];
    }
    __syncthreads();

    int lane = t & 31;
    int warp = t >> 5;
    int n0 = blockIdx.x * 32 + warp * 4;
    float* sA = sStage + warp * 328;
    float* sH = sA + 164;

    float a_lo[4], h_lo[4], a_hi[4], h_hi[4];
#pragma unroll
    for (int i = 0; i < 4; i++) {
        int b = (n0 + i) * 40;
        float av = g_agg2[b + lane];
        float hvv = g_h2[b + lane];
        a_lo[i] = av; h_lo[i] = hvv;
        sA[i * 41 + lane] = av;
        sH[i * 41 + lane] = hvv;
        if (lane < 8) {
            float avh = g_agg2[b + 32 + lane];
            float hvh = g_h2[b + 32 + lane];
            a_hi[i] = avh; h_hi[i] = hvh;
            sA[i * 41 + 32 + lane] = avh;
            sH[i * 41 + 32 + lane] = hvh;
        } else { a_hi[i] = 0.f; h_hi[i] = 0.f; }
    }
    __syncwarp();

    float gir[4], giz[4], gin[4], ghr[4], ghz[4], ghn[4];
    {
        float b0 = bih[lane], b1 = bih[40 + lane], b2 = bih[80 + lane];
        float b3 = bhh[lane], b4 = bhh[40 + lane], b5 = bhh[80 + lane];
#pragma unroll
        for (int i = 0; i < 4; i++) {
            gir[i] = b0; giz[i] = b1; gin[i] = b2;
            ghr[i] = b3; ghz[i] = b4; ghn[i] = b5;
        }
    }
    int hi_node = lane >> 3;
    int hi_col  = 32 + (lane & 7);
    float Gir = bih[hi_col], Giz = bih[40 + hi_col], Gin = bih[80 + hi_col];
    float Ghr = bhh[hi_col], Ghz = bhh[40 + hi_col], Ghn = bhh[80 + hi_col];
    const float* aN = sA + hi_node * 41;
    const float* hN = sH + hi_node * 41;

#pragma unroll 4
    for (int k = 0; k < 32; k++) {
        const float* wi = &sWi[k * 121];
        const float* wh = &sWh[k * 121];
        float wi0 = wi[lane], wi1 = wi[40 + lane], wi2 = wi[80 + lane];
        float wh0 = wh[lane], wh1 = wh[40 + lane], wh2 = wh[80 + lane];
        {
            float ak = aN[k], hk = hN[k];
            Gir = fmaf(ak, wi[hi_col],      Gir);
            Giz = fmaf(ak, wi[40 + hi_col], Giz);
            Gin = fmaf(ak, wi[80 + hi_col], Gin);
            Ghr = fmaf(hk, wh[hi_col],      Ghr);
            Ghz = fmaf(hk, wh[40 + hi_col], Ghz);
            Ghn = fmaf(hk, wh[80 + hi_col], Ghn);
        }
#pragma unroll
        for (int i = 0; i < 4; i++) {
            float ak = __shfl_sync(0xffffffffu, a_lo[i], k);
            float hk = __shfl_sync(0xffffffffu, h_lo[i], k);
            gir[i] = fmaf(ak, wi0, gir[i]);
            giz[i] = fmaf(ak, wi1, giz[i]);
            gin[i] = fmaf(ak, wi2, gin[i]);
            ghr[i] = fmaf(hk, wh0, ghr[i]);
            ghz[i] = fmaf(hk, wh1, ghz[i]);
            ghn[i] = fmaf(hk, wh2, ghn[i]);
        }
    }
#pragma unroll
    for (int k = 32; k < 40; k++) {
        const float* wi = &sWi[k * 121];
        const float* wh = &sWh[k * 121];
        float wi0 = wi[lane], wi1 = wi[40 + lane], wi2 = wi[80 + lane];
        float wh0 = wh[lane], wh1 = wh[40 + lane], wh2 = wh[80 + lane];
        {
            float ak = aN[k], hk = hN[k];
            Gir = fmaf(ak, wi[hi_col],      Gir);
            Giz = fmaf(ak, wi[40 + hi_col], Giz);
            Gin = fmaf(ak, wi[80 + hi_col], Gin);
            Ghr = fmaf(hk, wh[hi_col],      Ghr);
            Ghz = fmaf(hk, wh[40 + hi_col], Ghz);
            Ghn = fmaf(hk, wh[80 + hi_col], Ghn);
        }
#pragma unroll
        for (int i = 0; i < 4; i++) {
            float ak = __shfl_sync(0xffffffffu, a_hi[i], k - 32);
            float hk = __shfl_sync(0xffffffffu, h_hi[i], k - 32);
            gir[i] = fmaf(ak, wi0, gir[i]);
            giz[i] = fmaf(ak, wi1, giz[i]);
            gin[i] = fmaf(ak, wi2, gin[i]);
            ghr[i] = fmaf(hk, wh0, ghr[i]);
            ghz[i] = fmaf(hk, wh1, ghz[i]);
            ghn[i] = fmaf(hk, wh2, ghn[i]);
        }
    }

    float v1[4];
#pragma unroll
    for (int i = 0; i < 4; i++) {
        float r1 = 1.f / (1.f + __expf(-(gir[i] + ghr[i])));
        float z1 = 1.f / (1.f + __expf(-(giz[i] + ghz[i])));
        float n1 = tanhf(gin[i] + r1 * ghn[i]);
        v1[i] = (1.f - z1) * n1 + z1 * h_lo[i];
    }
    float v2;
    {
        float hvh = sH[hi_node * 41 + hi_col];
        float r2 = 1.f / (1.f + __expf(-(Gir + Ghr)));
        float z2 = 1.f / (1.f + __expf(-(Giz + Ghz)));
        float n2 = tanhf(Gin + r2 * Ghn);
        v2 = (1.f - z2) * n2 + z2 * hvh;
    }

    __syncwarp();
#pragma unroll
    for (int i = 0; i < 4; i++) sA[i * 41 + lane] = v1[i];
    sA[hi_node * 41 + hi_col] = v2;
    __syncwarp();

#pragma unroll
    for (int i = 0; i < 4; i++) {
        float x1 = sA[i * 41 + lane];
        float x2 = (lane < 8) ? sA[i * 41 + 32 + lane] : -FLT_MAX;
        float vmax = fmaxf(x1, x2);
#pragma unroll
        for (int o = 16; o > 0; o >>= 1)
            vmax = fmaxf(vmax, __shfl_xor_sync(0xffffffffu, vmax, o));
        float se = __expf(x1 - vmax) + ((lane < 8) ? __expf(x2 - vmax) : 0.f);
#pragma unroll
        for (int o = 16; o > 0; o >>= 1)
            se += __shfl_xor_sync(0xffffffffu, se, o);
        float ls = vmax + logf(se);

        int b = (n0 + i) * 40;
        out[b + lane] = x1 - ls;
        if (lane < 8) out[b + 32 + lane] = x2 - ls;
    }
}

// ---------------- launch ----------------
extern "C" void kernel_launch(void* const* d_in, const int* in_sizes, int n_in,
                              void* d_out, int out_size) {
    const float* x   = (const float*)d_in[0];
    const int*   ei  = (const int*)d_in[1];     // int32 (JAX x64 disabled)
    const float* ew  = (const float*)d_in[2];
    const float* W1p = (const float*)d_in[3];
    const float* W1m = (const float*)d_in[4];
    const float* g1wih = (const float*)d_in[5];
    const float* g1whh = (const float*)d_in[6];
    const float* g1bih = (const float*)d_in[7];
    const float* g1bhh = (const float*)d_in[8];
    const float* W2p = (const float*)d_in[9];
    const float* W2m = (const float*)d_in[10];
    const float* g2wih = (const float*)d_in[11];
    const float* g2whh = (const float*)d_in[12];
    const float* g2bih = (const float*)d_in[13];
    const float* g2bhh = (const float*)d_in[14];
    float* out = (float*)d_out;

    const int smem2 = (40 * 121 * 2 + 8 * 328) * 4;   // 49216 B
    cudaFuncSetAttribute(k_gru2, cudaFuncAttributeMaxDynamicSharedMemorySize, smem2);

    k_proj1<<<NB128, 128>>>(x, W1p, W1m);

    long long th1 = (long long)N_EDGES * 8;
    k_edge1<<<(int)((th1 + 255) / 256), 256>>>(ei, ew);

    k_gru1_proj2<<<NB128, 128>>>(g1wih, g1whh, g1bih, g1bhh, W2p, W2m);

    long long th2 = (long long)N_EDGES * 10;
    k_edge2<<<(int)((th2 + 255) / 256), 256>>>(ei, ew);

    k_gru2<<<NB256, 256, smem2>>>(out, g2wih, g2whh, g2bih, g2bhh);
}

// round 12
// speedup vs baseline: 1.1534x; 1.1011x over previous
#include <cuda_runtime.h>
#include <cstdint>
#include <float.h>

#define N_NODES 100000
#define N_EDGES 2000000
#define HID 32
#define NCLS 40
#define NB128 3125    // blocks of 128 threads, 4 warps x 8 nodes = 32 nodes/block
#define NB256 3125    // blocks of 256 threads, 8 warps x 4 nodes = 32 nodes/block

// ---------------- scratch (static device memory; no allocation) ----------------
__device__ float g_h1 [N_NODES * HID];
__device__ float g_agg1[N_NODES * HID];
__device__ float g_h2 [N_NODES * NCLS];
__device__ float g_agg2[N_NODES * NCLS];

// folded weights: C = W_msg @ wih.T, applied AFTER aggregation
__device__ float g_C1[32 * 96];    // [k][r]: C1[k][r] = sum_j W1m[k][j] * g1wih[r][j]
__device__ float g_C2[40 * 120];   // [k][r]: C2[k][r] = sum_j W2m[k][j] * g2wih[r][j]

__device__ __forceinline__ void red_add_v4(float* addr, float4 v) {
    asm volatile("red.global.add.v4.f32 [%0], {%1,%2,%3,%4};"
                 :: "l"(addr), "f"(v.x), "f"(v.y), "f"(v.z), "f"(v.w)
                 : "memory");
}

// ---------------- K0: prepack folded weights (one entry per thread) ------------
__global__ void k_prepack(const float* __restrict__ W1m,
                          const float* __restrict__ wih1,
                          const float* __restrict__ W2m,
                          const float* __restrict__ wih2) {
    int idx = blockIdx.x * 256 + threadIdx.x;
    if (idx < 32 * 96) {
        int k = idx / 96, r = idx % 96;
        float s = 0.f;
#pragma unroll 8
        for (int j = 0; j < 32; j++)
            s = fmaf(W1m[k * 32 + j], wih1[r * 32 + j], s);
        g_C1[idx] = s;
    } else if (idx < 32 * 96 + 40 * 120) {
        int i2 = idx - 32 * 96;
        int k = i2 / 120, r = i2 % 120;
        float s = 0.f;
#pragma unroll 8
        for (int j = 0; j < 40; j++)
            s = fmaf(W2m[k * 40 + j], wih2[r * 40 + j], s);
        g_C2[i2] = s;
    }
}

// ---------------- K1: h1 = x@W1p, zero agg1 (8 nodes/warp) ---------------------
__global__ void __launch_bounds__(128) k_proj1(const float* __restrict__ x,
                        const float* __restrict__ Wp) {
    __shared__ float sWp[1024];
    int t = threadIdx.x;
    for (int i = t; i < 1024; i += 128) sWp[i] = Wp[i];
    __syncthreads();

    int lane = t & 31;
    int n0 = blockIdx.x * 32 + (t >> 5) * 8;

    float xv[8], h[8];
#pragma unroll
    for (int i = 0; i < 8; i++) { xv[i] = x[(n0 + i) * 32 + lane]; h[i] = 0.f; }

#pragma unroll 8
    for (int k = 0; k < 32; k++) {
        float w = sWp[k * 32 + lane];
#pragma unroll
        for (int i = 0; i < 8; i++)
            h[i] = fmaf(__shfl_sync(0xffffffffu, xv[i], k), w, h[i]);
    }
#pragma unroll
    for (int i = 0; i < 8; i++) {
        int idx = (n0 + i) * 32 + lane;
        g_h1[idx] = h[i];
        g_agg1[idx] = 0.f;
    }
}

// ---------------- K2: edge scatter layer 1 — scatter h1 rows -------------------
__global__ void k_edge1(const int* __restrict__ ei,
                        const float* __restrict__ ew) {
    long long tid = (long long)blockIdx.x * blockDim.x + threadIdx.x;
    int e = (int)(tid >> 3);
    if (e >= N_EDGES) return;
    int q = (int)(tid & 7);
    int src = ei[e];
    int dst = ei[N_EDGES + e];
    float w = ew[e];
    const float4* hrow = (const float4*)&g_h1[src * 32];
    float4 m = hrow[q];
    m.x *= w; m.y *= w; m.z *= w; m.w *= w;
    red_add_v4(&g_agg1[dst * 32 + q * 4], m);
}

// ------- K3: GRU1 (gi = agg@C1) + ReLU + proj2, zero agg2 (8 nodes/warp) -------
__global__ void __launch_bounds__(128) k_gru1_proj2(
                             const float* __restrict__ whh,
                             const float* __restrict__ bih,
                             const float* __restrict__ bhh,
                             const float* __restrict__ Wp) {
    __shared__ float sWi[32 * 97]; // C1 [k][r], padded
    __shared__ float sWh[32 * 97]; // whh transposed [k][r], padded
    __shared__ float sWp[32 * 40];
    int t = threadIdx.x;
    for (int i = t; i < 96 * 32; i += 128) {
        int k = i / 96, r = i % 96;
        sWi[k * 97 + r] = g_C1[i];
    }
    for (int i = t; i < 96 * 32; i += 128) {
        int r = i >> 5, k = i & 31;       // whh row-major [96][32] -> [k][r]
        sWh[k * 97 + r] = whh[i];
    }
    for (int i = t; i < 32 * 40; i += 128) sWp[i] = Wp[i];
    __syncthreads();

    int lane = t & 31;
    int n0 = blockIdx.x * 32 + (t >> 5) * 8;

    float a[8], hv[8];
    float gir[8], giz[8], gin[8], ghr[8], ghz[8], ghn[8];
    {
        float b_ir = bih[lane], b_iz = bih[32 + lane], b_in = bih[64 + lane];
        float b_hr = bhh[lane], b_hz = bhh[32 + lane], b_hn = bhh[64 + lane];
#pragma unroll
        for (int i = 0; i < 8; i++) {
            int idx = (n0 + i) * 32 + lane;
            a[i] = g_agg1[idx];
            hv[i] = g_h1[idx];
            gir[i] = b_ir; giz[i] = b_iz; gin[i] = b_in;
            ghr[i] = b_hr; ghz[i] = b_hz; ghn[i] = b_hn;
        }
    }

#pragma unroll 4
    for (int k = 0; k < 32; k++) {
        const float* wi = &sWi[k * 97];
        const float* wh = &sWh[k * 97];
        float wir = wi[lane], wiz = wi[32 + lane], win = wi[64 + lane];
        float whr = wh[lane], whz = wh[32 + lane], whn = wh[64 + lane];
#pragma unroll
        for (int i = 0; i < 8; i++) {
            float ak = __shfl_sync(0xffffffffu, a[i],  k);
            float hk = __shfl_sync(0xffffffffu, hv[i], k);
            gir[i] = fmaf(ak, wir, gir[i]);
            giz[i] = fmaf(ak, wiz, giz[i]);
            gin[i] = fmaf(ak, win, gin[i]);
            ghr[i] = fmaf(hk, whr, ghr[i]);
            ghz[i] = fmaf(hk, whz, ghz[i]);
            ghn[i] = fmaf(hk, whn, ghn[i]);
        }
    }

    float hr[8];
#pragma unroll
    for (int i = 0; i < 8; i++) {
        float r = 1.f / (1.f + __expf(-(gir[i] + ghr[i])));
        float z = 1.f / (1.f + __expf(-(giz[i] + ghz[i])));
        float n = tanhf(gin[i] + r * ghn[i]);
        hr[i] = fmaxf((1.f - z) * n + z * hv[i], 0.f);
    }

    // ---- proj2: h2 = hr@Wp (32->40) only; no msg GEMM (folded into C2) ----
    int c2 = 32 + (lane & 7);
    float h_lo[8], h_hi[8];
#pragma unroll
    for (int i = 0; i < 8; i++) { h_lo[i] = 0.f; h_hi[i] = 0.f; }
#pragma unroll 4
    for (int k = 0; k < 32; k++) {
        float wlo = sWp[k * 40 + lane];
        float whi = sWp[k * 40 + c2];
#pragma unroll
        for (int i = 0; i < 8; i++) {
            float ak = __shfl_sync(0xffffffffu, hr[i], k);
            h_lo[i] = fmaf(ak, wlo, h_lo[i]);
            h_hi[i] = fmaf(ak, whi, h_hi[i]);
        }
    }
#pragma unroll
    for (int i = 0; i < 8; i++) {
        int base = (n0 + i) * 40;
        g_h2[base + lane] = h_lo[i];
        g_agg2[base + lane] = 0.f;
        if (lane < 8) {
            g_h2[base + 32 + lane] = h_hi[i];
            g_agg2[base + 32 + lane] = 0.f;
        }
    }
}

// ---------------- K4: edge scatter layer 2 — scatter h2 rows -------------------
__global__ void k_edge2(const int* __restrict__ ei,
                        const float* __restrict__ ew) {
    long long tid = (long long)blockIdx.x * blockDim.x + threadIdx.x;
    int e = (int)(tid / 10);
    if (e >= N_EDGES) return;
    int q = (int)(tid - (long long)e * 10);
    int src = ei[e];
    int dst = ei[N_EDGES + e];
    float w = ew[e];
    const float4* hrow = (const float4*)&g_h2[src * 40];
    float4 m = hrow[q];
    m.x *= w; m.y *= w; m.z *= w; m.w *= w;
    red_add_v4(&g_agg2[dst * 40 + q * 4], m);
}

// -------- K5: GRU2 (gi = agg@C2) + log_softmax (4 nodes/warp, exact-fit hi) ----
__global__ void __launch_bounds__(256) k_gru2(float* __restrict__ out,
                       const float* __restrict__ whh,
                       const float* __restrict__ bih,
                       const float* __restrict__ bhh) {
    extern __shared__ float dyn[];
    float* sWi = dyn;                  // C2 [k][r] padded stride 121
    float* sWh = sWi + 40 * 121;       // whh transposed [k][r]
    float* sStage = sWh + 40 * 121;    // 8 warps * 2 * 164

    int t = threadIdx.x;
    for (int i = t; i < 40 * 120; i += 256) {
        int k = i / 120, r = i % 120;
        sWi[k * 121 + r] = g_C2[i];
    }
    for (int i = t; i < 120 * 40; i += 256) {
        int r = i / 40, k = i % 40;     // whh row-major [120][40] -> [k][r]
        sWh[k * 121 + r] = whh[i];
    }
    __syncthreads();

    int lane = t & 31;
    int warp = t >> 5;
    int n0 = blockIdx.x * 32 + warp * 4;
    float* sA = sStage + warp * 328;
    float* sH = sA + 164;

    float a_lo[4], h_lo[4], a_hi[4], h_hi[4];
#pragma unroll
    for (int i = 0; i < 4; i++) {
        int b = (n0 + i) * 40;
        float av = g_agg2[b + lane];
        float hvv = g_h2[b + lane];
        a_lo[i] = av; h_lo[i] = hvv;
        sA[i * 41 + lane] = av;
        sH[i * 41 + lane] = hvv;
        if (lane < 8) {
            float avh = g_agg2[b + 32 + lane];
            float hvh = g_h2[b + 32 + lane];
            a_hi[i] = avh; h_hi[i] = hvh;
            sA[i * 41 + 32 + lane] = avh;
            sH[i * 41 + 32 + lane] = hvh;
        } else { a_hi[i] = 0.f; h_hi[i] = 0.f; }
    }
    __syncwarp();

    float gir[4], giz[4], gin[4], ghr[4], ghz[4], ghn[4];
    {
        float b0 = bih[lane], b1 = bih[40 + lane], b2 = bih[80 + lane];
        float b3 = bhh[lane], b4 = bhh[40 + lane], b5 = bhh[80 + lane];
#pragma unroll
        for (int i = 0; i < 4; i++) {
            gir[i] = b0; giz[i] = b1; gin[i] = b2;
            ghr[i] = b3; ghz[i] = b4; ghn[i] = b5;
        }
    }
    int hi_node = lane >> 3;
    int hi_col  = 32 + (lane & 7);
    float Gir = bih[hi_col], Giz = bih[40 + hi_col], Gin = bih[80 + hi_col];
    float Ghr = bhh[hi_col], Ghz = bhh[40 + hi_col], Ghn = bhh[80 + hi_col];
    const float* aN = sA + hi_node * 41;
    const float* hN = sH + hi_node * 41;

#pragma unroll 4
    for (int k = 0; k < 32; k++) {
        const float* wi = &sWi[k * 121];
        const float* wh = &sWh[k * 121];
        float wi0 = wi[lane], wi1 = wi[40 + lane], wi2 = wi[80 + lane];
        float wh0 = wh[lane], wh1 = wh[40 + lane], wh2 = wh[80 + lane];
        {
            float ak = aN[k], hk = hN[k];
            Gir = fmaf(ak, wi[hi_col],      Gir);
            Giz = fmaf(ak, wi[40 + hi_col], Giz);
            Gin = fmaf(ak, wi[80 + hi_col], Gin);
            Ghr = fmaf(hk, wh[hi_col],      Ghr);
            Ghz = fmaf(hk, wh[40 + hi_col], Ghz);
            Ghn = fmaf(hk, wh[80 + hi_col], Ghn);
        }
#pragma unroll
        for (int i = 0; i < 4; i++) {
            float ak = __shfl_sync(0xffffffffu, a_lo[i], k);
            float hk = __shfl_sync(0xffffffffu, h_lo[i], k);
            gir[i] = fmaf(ak, wi0, gir[i]);
            giz[i] = fmaf(ak, wi1, giz[i]);
            gin[i] = fmaf(ak, wi2, gin[i]);
            ghr[i] = fmaf(hk, wh0, ghr[i]);
            ghz[i] = fmaf(hk, wh1, ghz[i]);
            ghn[i] = fmaf(hk, wh2, ghn[i]);
        }
    }
#pragma unroll
    for (int k = 32; k < 40; k++) {
        const float* wi = &sWi[k * 121];
        const float* wh = &sWh[k * 121];
        float wi0 = wi[lane], wi1 = wi[40 + lane], wi2 = wi[80 + lane];
        float wh0 = wh[lane], wh1 = wh[40 + lane], wh2 = wh[80 + lane];
        {
            float ak = aN[k], hk = hN[k];
            Gir = fmaf(ak, wi[hi_col],      Gir);
            Giz = fmaf(ak, wi[40 + hi_col], Giz);
            Gin = fmaf(ak, wi[80 + hi_col], Gin);
            Ghr = fmaf(hk, wh[hi_col],      Ghr);
            Ghz = fmaf(hk, wh[40 + hi_col], Ghz);
            Ghn = fmaf(hk, wh[80 + hi_col], Ghn);
        }
#pragma unroll
        for (int i = 0; i < 4; i++) {
            float ak = __shfl_sync(0xffffffffu, a_hi[i], k - 32);
            float hk = __shfl_sync(0xffffffffu, h_hi[i], k - 32);
            gir[i] = fmaf(ak, wi0, gir[i]);
            giz[i] = fmaf(ak, wi1, giz[i]);
            gin[i] = fmaf(ak, wi2, gin[i]);
            ghr[i] = fmaf(hk, wh0, ghr[i]);
            ghz[i] = fmaf(hk, wh1, ghz[i]);
            ghn[i] = fmaf(hk, wh2, ghn[i]);
        }
    }

    float v1[4];
#pragma unroll
    for (int i = 0; i < 4; i++) {
        float r1 = 1.f / (1.f + __expf(-(gir[i] + ghr[i])));
        float z1 = 1.f / (1.f + __expf(-(giz[i] + ghz[i])));
        float n1 = tanhf(gin[i] + r1 * ghn[i]);
        v1[i] = (1.f - z1) * n1 + z1 * h_lo[i];
    }
    float v2;
    {
        float hvh = sH[hi_node * 41 + hi_col];
        float r2 = 1.f / (1.f + __expf(-(Gir + Ghr)));
        float z2 = 1.f / (1.f + __expf(-(Giz + Ghz)));
        float n2 = tanhf(Gin + r2 * Ghn);
        v2 = (1.f - z2) * n2 + z2 * hvh;
    }

    __syncwarp();
#pragma unroll
    for (int i = 0; i < 4; i++) sA[i * 41 + lane] = v1[i];
    sA[hi_node * 41 + hi_col] = v2;
    __syncwarp();

#pragma unroll
    for (int i = 0; i < 4; i++) {
        float x1 = sA[i * 41 + lane];
        float x2 = (lane < 8) ? sA[i * 41 + 32 + lane] : -FLT_MAX;
        float vmax = fmaxf(x1, x2);
#pragma unroll
        for (int o = 16; o > 0; o >>= 1)
            vmax = fmaxf(vmax, __shfl_xor_sync(0xffffffffu, vmax, o));
        float se = __expf(x1 - vmax) + ((lane < 8) ? __expf(x2 - vmax) : 0.f);
#pragma unroll
        for (int o = 16; o > 0; o >>= 1)
            se += __shfl_xor_sync(0xffffffffu, se, o);
        float ls = vmax + logf(se);

        int b = (n0 + i) * 40;
        out[b + lane] = x1 - ls;
        if (lane < 8) out[b + 32 + lane] = x2 - ls;
    }
}

// ---------------- launch ----------------
extern "C" void kernel_launch(void* const* d_in, const int* in_sizes, int n_in,
                              void* d_out, int out_size) {
    const float* x   = (const float*)d_in[0];
    const int*   ei  = (const int*)d_in[1];     // int32 (JAX x64 disabled)
    const float* ew  = (const float*)d_in[2];
    const float* W1p = (const float*)d_in[3];
    const float* W1m = (const float*)d_in[4];
    const float* g1wih = (const float*)d_in[5];
    const float* g1whh = (const float*)d_in[6];
    const float* g1bih = (const float*)d_in[7];
    const float* g1bhh = (const float*)d_in[8];
    const float* W2p = (const float*)d_in[9];
    const float* W2m = (const float*)d_in[10];
    const float* g2wih = (const float*)d_in[11];
    const float* g2whh = (const float*)d_in[12];
    const float* g2bih = (const float*)d_in[13];
    const float* g2bhh = (const float*)d_in[14];
    float* out = (float*)d_out;

    const int smem2 = (40 * 121 * 2 + 8 * 328) * 4;   // 49216 B
    cudaFuncSetAttribute(k_gru2, cudaFuncAttributeMaxDynamicSharedMemorySize, smem2);

    k_prepack<<<31, 256>>>(W1m, g1wih, W2m, g2wih);   // 7872 entries

    k_proj1<<<NB128, 128>>>(x, W1p);

    long long th1 = (long long)N_EDGES * 8;
    k_edge1<<<(int)((th1 + 255) / 256), 256>>>(ei, ew);

    k_gru1_proj2<<<NB128, 128>>>(g1whh, g1bih, g1bhh, W2p);

    long long th2 = (long long)N_EDGES * 10;
    k_edge2<<<(int)((th2 + 255) / 256), 256>>>(ei, ew);

    k_gru2<<<NB256, 256, smem2>>>(out, g2whh, g2bih, g2bhh);
}

// round 13
// speedup vs baseline: 1.2221x; 1.0595x over previous
#include <cuda_runtime.h>
#include <cstdint>
#include <float.h>

#define N_NODES 100000
#define N_EDGES 2000000
#define HID 32
#define NCLS 40
#define NB128 3125    // blocks of 128 threads, 4 warps x 8 nodes = 32 nodes/block
#define NB256 3125    // blocks of 256 threads, 8 warps x 4 nodes = 32 nodes/block

// ---------------- scratch (static device memory; no allocation) ----------------
__device__ float g_h1 [N_NODES * HID];
__device__ float g_agg1[N_NODES * HID];
__device__ float g_hr [N_NODES * HID];    // relu(gru1) — scattered for layer 2
__device__ float g_h2 [N_NODES * NCLS];   // GRU2 hidden-state input
__device__ float g_agg2[N_NODES * HID];   // raw 32-wide aggregation for layer 2

// folded weights
__device__ float g_C1[32 * 96];    // [k][r]: W1m @ wih1.T
__device__ float g_D [32 * 40];    // W2p @ W2m
__device__ float g_C2[32 * 120];   // [k][r]: W2p @ W2m @ wih2.T

__device__ __forceinline__ void red_add_v4(float* addr, float4 v) {
    asm volatile("red.global.add.v4.f32 [%0], {%1,%2,%3,%4};"
                 :: "l"(addr), "f"(v.x), "f"(v.y), "f"(v.z), "f"(v.w)
                 : "memory");
}

// ---------------- K0a: C1 = W1m@wih1.T ; D = W2p@W2m ----------------
__global__ void k_prepackA(const float* __restrict__ W1m,
                           const float* __restrict__ wih1,
                           const float* __restrict__ W2p,
                           const float* __restrict__ W2m) {
    int idx = blockIdx.x * 256 + threadIdx.x;
    if (idx < 32 * 96) {
        int k = idx / 96, r = idx % 96;
        float s = 0.f;
#pragma unroll 8
        for (int j = 0; j < 32; j++)
            s = fmaf(W1m[k * 32 + j], wih1[r * 32 + j], s);
        g_C1[idx] = s;
    } else if (idx < 32 * 96 + 32 * 40) {
        int i2 = idx - 32 * 96;
        int k = i2 / 40, l = i2 % 40;
        float s = 0.f;
#pragma unroll 8
        for (int j = 0; j < 40; j++)
            s = fmaf(W2p[k * 40 + j], W2m[j * 40 + l], s);
        g_D[i2] = s;
    }
}

// ---------------- K0b: C2 = D @ wih2.T (32 x 120) ----------------
__global__ void k_prepackB(const float* __restrict__ wih2) {
    int idx = blockIdx.x * 256 + threadIdx.x;
    if (idx < 32 * 120) {
        int k = idx / 120, r = idx % 120;
        float s = 0.f;
#pragma unroll 8
        for (int l = 0; l < 40; l++)
            s = fmaf(g_D[k * 40 + l], wih2[r * 40 + l], s);
        g_C2[idx] = s;
    }
}

// ---------------- K1: h1 = x@W1p, zero agg1 (8 nodes/warp) ---------------------
__global__ void __launch_bounds__(128) k_proj1(const float* __restrict__ x,
                        const float* __restrict__ Wp) {
    __shared__ float sWp[1024];
    int t = threadIdx.x;
    for (int i = t; i < 1024; i += 128) sWp[i] = Wp[i];
    __syncthreads();

    int lane = t & 31;
    int n0 = blockIdx.x * 32 + (t >> 5) * 8;

    float xv[8], h[8];
#pragma unroll
    for (int i = 0; i < 8; i++) { xv[i] = x[(n0 + i) * 32 + lane]; h[i] = 0.f; }

#pragma unroll 8
    for (int k = 0; k < 32; k++) {
        float w = sWp[k * 32 + lane];
#pragma unroll
        for (int i = 0; i < 8; i++)
            h[i] = fmaf(__shfl_sync(0xffffffffu, xv[i], k), w, h[i]);
    }
#pragma unroll
    for (int i = 0; i < 8; i++) {
        int idx = (n0 + i) * 32 + lane;
        g_h1[idx] = h[i];
        g_agg1[idx] = 0.f;
    }
}

// ---------------- K2: edge scatter layer 1 — scatter h1 rows -------------------
__global__ void k_edge1(const int* __restrict__ ei,
                        const float* __restrict__ ew) {
    long long tid = (long long)blockIdx.x * blockDim.x + threadIdx.x;
    int e = (int)(tid >> 3);
    if (e >= N_EDGES) return;
    int q = (int)(tid & 7);
    int src = ei[e];
    int dst = ei[N_EDGES + e];
    float w = ew[e];
    const float4* hrow = (const float4*)&g_h1[src * 32];
    float4 m = hrow[q];
    m.x *= w; m.y *= w; m.z *= w; m.w *= w;
    red_add_v4(&g_agg1[dst * 32 + q * 4], m);
}

// ------- K3: GRU1 (gi = agg@C1) + ReLU + proj2, zero agg2 (8 nodes/warp) -------
__global__ void __launch_bounds__(128) k_gru1_proj2(
                             const float* __restrict__ whh,
                             const float* __restrict__ bih,
                             const float* __restrict__ bhh,
                             const float* __restrict__ Wp) {
    __shared__ float sWi[32 * 97]; // C1 [k][r], padded
    __shared__ float sWh[32 * 97]; // whh transposed [k][r], padded
    __shared__ float sWp[32 * 40];
    int t = threadIdx.x;
    for (int i = t; i < 96 * 32; i += 128) {
        int k = i / 96, r = i % 96;
        sWi[k * 97 + r] = g_C1[i];
    }
    for (int i = t; i < 96 * 32; i += 128) {
        int r = i >> 5, k = i & 31;       // whh row-major [96][32] -> [k][r]
        sWh[k * 97 + r] = whh[i];
    }
    for (int i = t; i < 32 * 40; i += 128) sWp[i] = Wp[i];
    __syncthreads();

    int lane = t & 31;
    int n0 = blockIdx.x * 32 + (t >> 5) * 8;

    float a[8], hv[8];
    float gir[8], giz[8], gin[8], ghr[8], ghz[8], ghn[8];
    {
        float b_ir = bih[lane], b_iz = bih[32 + lane], b_in = bih[64 + lane];
        float b_hr = bhh[lane], b_hz = bhh[32 + lane], b_hn = bhh[64 + lane];
#pragma unroll
        for (int i = 0; i < 8; i++) {
            int idx = (n0 + i) * 32 + lane;
            a[i] = g_agg1[idx];
            hv[i] = g_h1[idx];
            gir[i] = b_ir; giz[i] = b_iz; gin[i] = b_in;
            ghr[i] = b_hr; ghz[i] = b_hz; ghn[i] = b_hn;
        }
    }

#pragma unroll 4
    for (int k = 0; k < 32; k++) {
        const float* wi = &sWi[k * 97];
        const float* wh = &sWh[k * 97];
        float wir = wi[lane], wiz = wi[32 + lane], win = wi[64 + lane];
        float whr = wh[lane], whz = wh[32 + lane], whn = wh[64 + lane];
#pragma unroll
        for (int i = 0; i < 8; i++) {
            float ak = __shfl_sync(0xffffffffu, a[i],  k);
            float hk = __shfl_sync(0xffffffffu, hv[i], k);
            gir[i] = fmaf(ak, wir, gir[i]);
            giz[i] = fmaf(ak, wiz, giz[i]);
            gin[i] = fmaf(ak, win, gin[i]);
            ghr[i] = fmaf(hk, whr, ghr[i]);
            ghz[i] = fmaf(hk, whz, ghz[i]);
            ghn[i] = fmaf(hk, whn, ghn[i]);
        }
    }

    float hr[8];
#pragma unroll
    for (int i = 0; i < 8; i++) {
        float r = 1.f / (1.f + __expf(-(gir[i] + ghr[i])));
        float z = 1.f / (1.f + __expf(-(giz[i] + ghz[i])));
        float n = tanhf(gin[i] + r * ghn[i]);
        hr[i] = fmaxf((1.f - z) * n + z * hv[i], 0.f);
    }

    // store hr (scattered by edge2) + zero agg2 (32-wide)
#pragma unroll
    for (int i = 0; i < 8; i++) {
        int idx = (n0 + i) * 32 + lane;
        g_hr[idx] = hr[i];
        g_agg2[idx] = 0.f;
    }

    // ---- h2 = hr@Wp (32->40): GRU2 hidden-state input ----
    int c2 = 32 + (lane & 7);
    float h_lo[8], h_hi[8];
#pragma unroll
    for (int i = 0; i < 8; i++) { h_lo[i] = 0.f; h_hi[i] = 0.f; }
#pragma unroll 4
    for (int k = 0; k < 32; k++) {
        float wlo = sWp[k * 40 + lane];
        float whi = sWp[k * 40 + c2];
#pragma unroll
        for (int i = 0; i < 8; i++) {
            float ak = __shfl_sync(0xffffffffu, hr[i], k);
            h_lo[i] = fmaf(ak, wlo, h_lo[i]);
            h_hi[i] = fmaf(ak, whi, h_hi[i]);
        }
    }
#pragma unroll
    for (int i = 0; i < 8; i++) {
        int base = (n0 + i) * 40;
        g_h2[base + lane] = h_lo[i];
        if (lane < 8) g_h2[base + 32 + lane] = h_hi[i];
    }
}

// ---------------- K4: edge scatter layer 2 — scatter hr rows (32-wide) ---------
__global__ void k_edge2(const int* __restrict__ ei,
                        const float* __restrict__ ew) {
    long long tid = (long long)blockIdx.x * blockDim.x + threadIdx.x;
    int e = (int)(tid >> 3);
    if (e >= N_EDGES) return;
    int q = (int)(tid & 7);
    int src = ei[e];
    int dst = ei[N_EDGES + e];
    float w = ew[e];
    const float4* hrow = (const float4*)&g_hr[src * 32];
    float4 m = hrow[q];
    m.x *= w; m.y *= w; m.z *= w; m.w *= w;
    red_add_v4(&g_agg2[dst * 32 + q * 4], m);
}

// -------- K5: GRU2 (gi = agg32@C2) + log_softmax (4 nodes/warp, exact-fit hi) --
__global__ void __launch_bounds__(256) k_gru2(float* __restrict__ out,
                       const float* __restrict__ whh,
                       const float* __restrict__ bih,
                       const float* __restrict__ bhh) {
    extern __shared__ float dyn[];
    float* sWi = dyn;                  // C2 [k][r], k<32, padded stride 121
    float* sWh = sWi + 32 * 121;       // whh transposed [k][r], k<40
    float* sStage = sWh + 40 * 121;    // 8 warps * (132 + 164)

    int t = threadIdx.x;
    for (int i = t; i < 32 * 120; i += 256) {
        int k = i / 120, r = i % 120;
        sWi[k * 121 + r] = g_C2[i];
    }
    for (int i = t; i < 120 * 40; i += 256) {
        int r = i / 40, k = i % 40;     // whh row-major [120][40] -> [k][r]
        sWh[k * 121 + r] = whh[i];
    }
    __syncthreads();

    int lane = t & 31;
    int warp = t >> 5;
    int n0 = blockIdx.x * 32 + warp * 4;
    float* sA = sStage + warp * 296;   // 4*33 a (32-wide)
    float* sH = sA + 132;              // 4*41 h (40-wide)

    float a_lo[4], h_lo[4], h_hi[4];
#pragma unroll
    for (int i = 0; i < 4; i++) {
        float av = g_agg2[(n0 + i) * 32 + lane];
        a_lo[i] = av;
        sA[i * 33 + lane] = av;
        int b = (n0 + i) * 40;
        float hvv = g_h2[b + lane];
        h_lo[i] = hvv;
        sH[i * 41 + lane] = hvv;
        if (lane < 8) {
            float hvh = g_h2[b + 32 + lane];
            h_hi[i] = hvh;
            sH[i * 41 + 32 + lane] = hvh;
        } else h_hi[i] = 0.f;
    }
    __syncwarp();

    float gir[4], giz[4], gin[4], ghr[4], ghz[4], ghn[4];
    {
        float b0 = bih[lane], b1 = bih[40 + lane], b2 = bih[80 + lane];
        float b3 = bhh[lane], b4 = bhh[40 + lane], b5 = bhh[80 + lane];
#pragma unroll
        for (int i = 0; i < 4; i++) {
            gir[i] = b0; giz[i] = b1; gin[i] = b2;
            ghr[i] = b3; ghz[i] = b4; ghn[i] = b5;
        }
    }
    int hi_node = lane >> 3;
    int hi_col  = 32 + (lane & 7);
    float Gir = bih[hi_col], Giz = bih[40 + hi_col], Gin = bih[80 + hi_col];
    float Ghr = bhh[hi_col], Ghz = bhh[40 + hi_col], Ghn = bhh[80 + hi_col];
    const float* aN = sA + hi_node * 33;
    const float* hN = sH + hi_node * 41;

#pragma unroll 4
    for (int k = 0; k < 32; k++) {
        const float* wi = &sWi[k * 121];
        const float* wh = &sWh[k * 121];
        float wi0 = wi[lane], wi1 = wi[40 + lane], wi2 = wi[80 + lane];
        float wh0 = wh[lane], wh1 = wh[40 + lane], wh2 = wh[80 + lane];
        {
            float ak = aN[k], hk = hN[k];
            Gir = fmaf(ak, wi[hi_col],      Gir);
            Giz = fmaf(ak, wi[40 + hi_col], Giz);
            Gin = fmaf(ak, wi[80 + hi_col], Gin);
            Ghr = fmaf(hk, wh[hi_col],      Ghr);
            Ghz = fmaf(hk, wh[40 + hi_col], Ghz);
            Ghn = fmaf(hk, wh[80 + hi_col], Ghn);
        }
#pragma unroll
        for (int i = 0; i < 4; i++) {
            float ak = __shfl_sync(0xffffffffu, a_lo[i], k);
            float hk = __shfl_sync(0xffffffffu, h_lo[i], k);
            gir[i] = fmaf(ak, wi0, gir[i]);
            giz[i] = fmaf(ak, wi1, giz[i]);
            gin[i] = fmaf(ak, wi2, gin[i]);
            ghr[i] = fmaf(hk, wh0, ghr[i]);
            ghz[i] = fmaf(hk, wh1, ghz[i]);
            ghn[i] = fmaf(hk, wh2, ghn[i]);
        }
    }
    // h-side only for k = 32..39 (a is 32-wide after the fold)
#pragma unroll
    for (int k = 32; k < 40; k++) {
        const float* wh = &sWh[k * 121];
        float wh0 = wh[lane], wh1 = wh[40 + lane], wh2 = wh[80 + lane];
        {
            float hk = hN[k];
            Ghr = fmaf(hk, wh[hi_col],      Ghr);
            Ghz = fmaf(hk, wh[40 + hi_col], Ghz);
            Ghn = fmaf(hk, wh[80 + hi_col], Ghn);
        }
#pragma unroll
        for (int i = 0; i < 4; i++) {
            float hk = __shfl_sync(0xffffffffu, h_hi[i], k - 32);
            ghr[i] = fmaf(hk, wh0, ghr[i]);
            ghz[i] = fmaf(hk, wh1, ghz[i]);
            ghn[i] = fmaf(hk, wh2, ghn[i]);
        }
    }

    float v1[4];
#pragma unroll
    for (int i = 0; i < 4; i++) {
        float r1 = 1.f / (1.f + __expf(-(gir[i] + ghr[i])));
        float z1 = 1.f / (1.f + __expf(-(giz[i] + ghz[i])));
        float n1 = tanhf(gin[i] + r1 * ghn[i]);
        v1[i] = (1.f - z1) * n1 + z1 * h_lo[i];
    }
    float v2;
    {
        float hvh = sH[hi_node * 41 + hi_col];
        float r2 = 1.f / (1.f + __expf(-(Gir + Ghr)));
        float z2 = 1.f / (1.f + __expf(-(Giz + Ghz)));
        float n2 = tanhf(Gin + r2 * Ghn);
        v2 = (1.f - z2) * n2 + z2 * hvh;
    }

    __syncwarp();
#pragma unroll
    for (int i = 0; i < 4; i++) sH[i * 41 + lane] = v1[i];   // reuse sH for v
    sH[hi_node * 41 + hi_col] = v2;
    __syncwarp();

#pragma unroll
    for (int i = 0; i < 4; i++) {
        float x1 = sH[i * 41 + lane];
        float x2 = (lane < 8) ? sH[i * 41 + 32 + lane] : -FLT_MAX;
        float vmax = fmaxf(x1, x2);
#pragma unroll
        for (int o = 16; o > 0; o >>= 1)
            vmax = fmaxf(vmax, __shfl_xor_sync(0xffffffffu, vmax, o));
        float se = __expf(x1 - vmax) + ((lane < 8) ? __expf(x2 - vmax) : 0.f);
#pragma unroll
        for (int o = 16; o > 0; o >>= 1)
            se += __shfl_xor_sync(0xffffffffu, se, o);
        float ls = vmax + logf(se);

        int b = (n0 + i) * 40;
        out[b + lane] = x1 - ls;
        if (lane < 8) out[b + 32 + lane] = x2 - ls;
    }
}

// ---------------- launch ----------------
extern "C" void kernel_launch(void* const* d_in, const int* in_sizes, int n_in,
                              void* d_out, int out_size) {
    const float* x   = (const float*)d_in[0];
    const int*   ei  = (const int*)d_in[1];     // int32 (JAX x64 disabled)
    const float* ew  = (const float*)d_in[2];
    const float* W1p = (const float*)d_in[3];
    const float* W1m = (const float*)d_in[4];
    const float* g1wih = (const float*)d_in[5];
    const float* g1whh = (const float*)d_in[6];
    const float* g1bih = (const float*)d_in[7];
    const float* g1bhh = (const float*)d_in[8];
    const float* W2p = (const float*)d_in[9];
    const float* W2m = (const float*)d_in[10];
    const float* g2wih = (const float*)d_in[11];
    const float* g2whh = (const float*)d_in[12];
    const float* g2bih = (const float*)d_in[13];
    const float* g2bhh = (const float*)d_in[14];
    float* out = (float*)d_out;

    const int smem2 = (32 * 121 + 40 * 121 + 8 * 296) * 4;   // 44320 B
    cudaFuncSetAttribute(k_gru2, cudaFuncAttributeMaxDynamicSharedMemorySize, smem2);

    k_prepackA<<<17, 256>>>(W1m, g1wih, W2p, W2m);   // 3072 + 1280 entries
    k_prepackB<<<15, 256>>>(g2wih);                  // 3840 entries

    k_proj1<<<NB128, 128>>>(x, W1p);

    long long th1 = (long long)N_EDGES * 8;
    k_edge1<<<(int)((th1 + 255) / 256), 256>>>(ei, ew);

    k_gru1_proj2<<<NB128, 128>>>(g1whh, g1bih, g1bhh, W2p);

    k_edge2<<<(int)((th1 + 255) / 256), 256>>>(ei, ew);

    k_gru2<<<NB256, 256, smem2>>>(out, g2whh, g2bih, g2bhh);
}

// round 16
// speedup vs baseline: 1.2571x; 1.0287x over previous
#include <cuda_runtime.h>
#include <cstdint>
#include <float.h>

#define N_NODES 100000
#define N_EDGES 2000000
#define HID 32
#define NCLS 40
#define NB128 3125    // blocks of 128 threads, 4 warps x 8 nodes = 32 nodes/block
#define NB256 3125    // blocks of 256 threads, 8 warps x 4 nodes = 32 nodes/block

// ---------------- scratch (static device memory; no allocation) ----------------
__device__ float g_h1 [N_NODES * HID];
__device__ float g_agg1[N_NODES * HID];
__device__ float g_hr [N_NODES * HID];    // relu(gru1) — scattered for layer 2
__device__ float g_h2 [N_NODES * NCLS];   // GRU2 hidden-state (blend only)
__device__ float g_agg2[N_NODES * HID];   // raw 32-wide aggregation for layer 2

// folded weights
__device__ float g_C1[32 * 96];    // W1m @ wih1.T
__device__ float g_D [32 * 40];    // W2p @ W2m
__device__ float g_C2[32 * 120];   // W2p @ W2m @ wih2.T
__device__ float g_E2[32 * 120];   // W2p @ whh2.T

__device__ __forceinline__ void red_add_v4(float* addr, float4 v) {
    asm volatile("red.global.add.v4.f32 [%0], {%1,%2,%3,%4};"
                 :: "l"(addr), "f"(v.x), "f"(v.y), "f"(v.z), "f"(v.w)
                 : "memory");
}

// ---------------- K0a: C1 = W1m@wih1.T ; D = W2p@W2m ----------------
__global__ void k_prepackA(const float* __restrict__ W1m,
                           const float* __restrict__ wih1,
                           const float* __restrict__ W2p,
                           const float* __restrict__ W2m) {
    int idx = blockIdx.x * 256 + threadIdx.x;
    if (idx < 32 * 96) {
        int k = idx / 96, r = idx % 96;
        float s = 0.f;
#pragma unroll 8
        for (int j = 0; j < 32; j++)
            s = fmaf(W1m[k * 32 + j], wih1[r * 32 + j], s);
        g_C1[idx] = s;
    } else if (idx < 32 * 96 + 32 * 40) {
        int i2 = idx - 32 * 96;
        int k = i2 / 40, l = i2 % 40;
        float s = 0.f;
#pragma unroll 8
        for (int j = 0; j < 40; j++)
            s = fmaf(W2p[k * 40 + j], W2m[j * 40 + l], s);
        g_D[i2] = s;
    }
}

// ---------------- K0b: C2 = D@wih2.T ; E2 = W2p@whh2.T (each 32x120) ----------
__global__ void k_prepackB(const float* __restrict__ wih2,
                           const float* __restrict__ W2p,
                           const float* __restrict__ whh2) {
    int idx = blockIdx.x * 256 + threadIdx.x;
    if (idx < 32 * 120) {
        int k = idx / 120, r = idx % 120;
        float s = 0.f;
#pragma unroll 8
        for (int l = 0; l < 40; l++)
            s = fmaf(g_D[k * 40 + l], wih2[r * 40 + l], s);
        g_C2[idx] = s;
    } else if (idx < 2 * 32 * 120) {
        int i2 = idx - 32 * 120;
        int k = i2 / 120, r = i2 % 120;
        float s = 0.f;
#pragma unroll 8
        for (int j = 0; j < 40; j++)
            s = fmaf(W2p[k * 40 + j], whh2[r * 40 + j], s);
        g_E2[i2] = s;
    }
}

// ---------------- K1: h1 = x@W1p, zero agg1 (8 nodes/warp) ---------------------
__global__ void __launch_bounds__(128) k_proj1(const float* __restrict__ x,
                        const float* __restrict__ Wp) {
    __shared__ float sWp[1024];
    int t = threadIdx.x;
    for (int i = t; i < 1024; i += 128) sWp[i] = Wp[i];
    __syncthreads();

    int lane = t & 31;
    int n0 = blockIdx.x * 32 + (t >> 5) * 8;

    float xv[8], h[8];
#pragma unroll
    for (int i = 0; i < 8; i++) { xv[i] = x[(n0 + i) * 32 + lane]; h[i] = 0.f; }

#pragma unroll 8
    for (int k = 0; k < 32; k++) {
        float w = sWp[k * 32 + lane];
#pragma unroll
        for (int i = 0; i < 8; i++)
            h[i] = fmaf(__shfl_sync(0xffffffffu, xv[i], k), w, h[i]);
    }
#pragma unroll
    for (int i = 0; i < 8; i++) {
        int idx = (n0 + i) * 32 + lane;
        g_h1[idx] = h[i];
        g_agg1[idx] = 0.f;
    }
}

// ---------------- K2: edge scatter layer 1 — scatter h1 rows -------------------
__global__ void k_edge1(const int* __restrict__ ei,
                        const float* __restrict__ ew) {
    long long tid = (long long)blockIdx.x * blockDim.x + threadIdx.x;
    int e = (int)(tid >> 3);
    if (e >= N_EDGES) return;
    int q = (int)(tid & 7);
    int src = ei[e];
    int dst = ei[N_EDGES + e];
    float w = ew[e];
    const float4* hrow = (const float4*)&g_h1[src * 32];
    float4 m = hrow[q];
    m.x *= w; m.y *= w; m.z *= w; m.w *= w;
    red_add_v4(&g_agg1[dst * 32 + q * 4], m);
}

// ------- K3: GRU1 (gi = agg@C1) + ReLU + proj2, zero agg2 (8 nodes/warp) -------
__global__ void __launch_bounds__(128) k_gru1_proj2(
                             const float* __restrict__ whh,
                             const float* __restrict__ bih,
                             const float* __restrict__ bhh,
                             const float* __restrict__ Wp) {
    __shared__ float sWi[32 * 97]; // C1 [k][r], padded
    __shared__ float sWh[32 * 97]; // whh transposed [k][r], padded
    __shared__ float sWp[32 * 40];
    int t = threadIdx.x;
    for (int i = t; i < 96 * 32; i += 128) {
        int k = i / 96, r = i % 96;
        sWi[k * 97 + r] = g_C1[i];
    }
    for (int i = t; i < 96 * 32; i += 128) {
        int r = i >> 5, k = i & 31;       // whh row-major [96][32] -> [k][r]
        sWh[k * 97 + r] = whh[i];
    }
    for (int i = t; i < 32 * 40; i += 128) sWp[i] = Wp[i];
    __syncthreads();

    int lane = t & 31;
    int n0 = blockIdx.x * 32 + (t >> 5) * 8;

    float a[8], hv[8];
    float gir[8], giz[8], gin[8], ghr[8], ghz[8], ghn[8];
    {
        float b_ir = bih[lane], b_iz = bih[32 + lane], b_in = bih[64 + lane];
        float b_hr = bhh[lane], b_hz = bhh[32 + lane], b_hn = bhh[64 + lane];
#pragma unroll
        for (int i = 0; i < 8; i++) {
            int idx = (n0 + i) * 32 + lane;
            a[i] = g_agg1[idx];
            hv[i] = g_h1[idx];
            gir[i] = b_ir; giz[i] = b_iz; gin[i] = b_in;
            ghr[i] = b_hr; ghz[i] = b_hz; ghn[i] = b_hn;
        }
    }

#pragma unroll 4
    for (int k = 0; k < 32; k++) {
        const float* wi = &sWi[k * 97];
        const float* wh = &sWh[k * 97];
        float wir = wi[lane], wiz = wi[32 + lane], win = wi[64 + lane];
        float whr = wh[lane], whz = wh[32 + lane], whn = wh[64 + lane];
#pragma unroll
        for (int i = 0; i < 8; i++) {
            float ak = __shfl_sync(0xffffffffu, a[i],  k);
            float hk = __shfl_sync(0xffffffffu, hv[i], k);
            gir[i] = fmaf(ak, wir, gir[i]);
            giz[i] = fmaf(ak, wiz, giz[i]);
            gin[i] = fmaf(ak, win, gin[i]);
            ghr[i] = fmaf(hk, whr, ghr[i]);
            ghz[i] = fmaf(hk, whz, ghz[i]);
            ghn[i] = fmaf(hk, whn, ghn[i]);
        }
    }

    float hr[8];
#pragma unroll
    for (int i = 0; i < 8; i++) {
        float r = 1.f / (1.f + __expf(-(gir[i] + ghr[i])));
        float z = 1.f / (1.f + __expf(-(giz[i] + ghz[i])));
        float n = tanhf(gin[i] + r * ghn[i]);
        hr[i] = fmaxf((1.f - z) * n + z * hv[i], 0.f);
    }

    // store hr (scattered by edge2; contracted by gru2) + zero agg2 (32-wide)
#pragma unroll
    for (int i = 0; i < 8; i++) {
        int idx = (n0 + i) * 32 + lane;
        g_hr[idx] = hr[i];
        g_agg2[idx] = 0.f;
    }

    // ---- h2 = hr@Wp (32->40): GRU2 blend input ----
    int c2 = 32 + (lane & 7);
    float h_lo[8], h_hi[8];
#pragma unroll
    for (int i = 0; i < 8; i++) { h_lo[i] = 0.f; h_hi[i] = 0.f; }
#pragma unroll 4
    for (int k = 0; k < 32; k++) {
        float wlo = sWp[k * 40 + lane];
        float whi = sWp[k * 40 + c2];
#pragma unroll
        for (int i = 0; i < 8; i++) {
            float ak = __shfl_sync(0xffffffffu, hr[i], k);
            h_lo[i] = fmaf(ak, wlo, h_lo[i]);
            h_hi[i] = fmaf(ak, whi, h_hi[i]);
        }
    }
#pragma unroll
    for (int i = 0; i < 8; i++) {
        int base = (n0 + i) * 40;
        g_h2[base + lane] = h_lo[i];
        if (lane < 8) g_h2[base + 32 + lane] = h_hi[i];
    }
}

// ---------------- K4: edge scatter layer 2 — scatter hr rows (32-wide) ---------
__global__ void k_edge2(const int* __restrict__ ei,
                        const float* __restrict__ ew) {
    long long tid = (long long)blockIdx.x * blockDim.x + threadIdx.x;
    int e = (int)(tid >> 3);
    if (e >= N_EDGES) return;
    int q = (int)(tid & 7);
    int src = ei[e];
    int dst = ei[N_EDGES + e];
    float w = ew[e];
    const float4* hrow = (const float4*)&g_hr[src * 32];
    float4 m = hrow[q];
    m.x *= w; m.y *= w; m.z *= w; m.w *= w;
    red_add_v4(&g_agg2[dst * 32 + q * 4], m);
}

// -- K5: GRU2 (gi = agg@C2, gh = hr@E2) + log_softmax (4 nodes/warp, exact hi) --
__global__ void __launch_bounds__(256) k_gru2(float* __restrict__ out,
                       const float* __restrict__ bih,
                       const float* __restrict__ bhh) {
    extern __shared__ float dyn[];
    float* sWi = dyn;                  // C2 [k][r], k<32, padded stride 121
    float* sWe = sWi + 32 * 121;       // E2 [k][r], k<32, padded stride 121
    float* sStage = sWe + 32 * 121;    // 8 warps * (132 + 132 + 164)

    int t = threadIdx.x;
    for (int i = t; i < 32 * 120; i += 256) {
        int k = i / 120, r = i % 120;
        sWi[k * 121 + r] = g_C2[i];
        sWe[k * 121 + r] = g_E2[i];
    }
    __syncthreads();

    int lane = t & 31;
    int warp = t >> 5;
    int n0 = blockIdx.x * 32 + warp * 4;
    float* sA = sStage + warp * 428;   // 4*33 agg (32-wide)
    float* sR = sA + 132;              // 4*33 hr  (32-wide)
    float* sH = sR + 132;              // 4*41 h2  (40-wide, blend only)

    float a_lo[4], r_lo[4], h_lo[4];
#pragma unroll
    for (int i = 0; i < 4; i++) {
        int b32 = (n0 + i) * 32;
        float av = g_agg2[b32 + lane];
        float rv = g_hr[b32 + lane];
        a_lo[i] = av; r_lo[i] = rv;
        sA[i * 33 + lane] = av;
        sR[i * 33 + lane] = rv;
        int b = (n0 + i) * 40;
        float hvv = g_h2[b + lane];
        h_lo[i] = hvv;
        sH[i * 41 + lane] = hvv;
        if (lane < 8) sH[i * 41 + 32 + lane] = g_h2[b + 32 + lane];
    }
    __syncwarp();

    float gir[4], giz[4], gin[4], ghr[4], ghz[4], ghn[4];
    {
        float b0 = bih[lane], b1 = bih[40 + lane], b2 = bih[80 + lane];
        float b3 = bhh[lane], b4 = bhh[40 + lane], b5 = bhh[80 + lane];
#pragma unroll
        for (int i = 0; i < 4; i++) {
            gir[i] = b0; giz[i] = b1; gin[i] = b2;
            ghr[i] = b3; ghz[i] = b4; ghn[i] = b5;
        }
    }
    int hi_node = lane >> 3;
    int hi_col  = 32 + (lane & 7);
    float Gir = bih[hi_col], Giz = bih[40 + hi_col], Gin = bih[80 + hi_col];
    float Ghr = bhh[hi_col], Ghz = bhh[40 + hi_col], Ghn = bhh[80 + hi_col];
    const float* aN = sA + hi_node * 33;
    const float* rN = sR + hi_node * 33;

#pragma unroll 4
    for (int k = 0; k < 32; k++) {
        const float* wi = &sWi[k * 121];
        const float* we = &sWe[k * 121];
        float wi0 = wi[lane], wi1 = wi[40 + lane], wi2 = wi[80 + lane];
        float we0 = we[lane], we1 = we[40 + lane], we2 = we[80 + lane];
        {
            float ak = aN[k], rk = rN[k];
            Gir = fmaf(ak, wi[hi_col],      Gir);
            Giz = fmaf(ak, wi[40 + hi_col], Giz);
            Gin = fmaf(ak, wi[80 + hi_col], Gin);
            Ghr = fmaf(rk, we[hi_col],      Ghr);
            Ghz = fmaf(rk, we[40 + hi_col], Ghz);
            Ghn = fmaf(rk, we[80 + hi_col], Ghn);
        }
#pragma unroll
        for (int i = 0; i < 4; i++) {
            float ak = __shfl_sync(0xffffffffu, a_lo[i], k);
            float rk = __shfl_sync(0xffffffffu, r_lo[i], k);
            gir[i] = fmaf(ak, wi0, gir[i]);
            giz[i] = fmaf(ak, wi1, giz[i]);
            gin[i] = fmaf(ak, wi2, gin[i]);
            ghr[i] = fmaf(rk, we0, ghr[i]);
            ghz[i] = fmaf(rk, we1, ghz[i]);
            ghn[i] = fmaf(rk, we2, ghn[i]);
        }
    }

    float v1[4];
#pragma unroll
    for (int i = 0; i < 4; i++) {
        float r1 = 1.f / (1.f + __expf(-(gir[i] + ghr[i])));
        float z1 = 1.f / (1.f + __expf(-(giz[i] + ghz[i])));
        float n1 = tanhf(gin[i] + r1 * ghn[i]);
        v1[i] = (1.f - z1) * n1 + z1 * h_lo[i];
    }
    float v2;
    {
        float hvh = sH[hi_node * 41 + hi_col];
        float r2 = 1.f / (1.f + __expf(-(Gir + Ghr)));
        float z2 = 1.f / (1.f + __expf(-(Giz + Ghz)));
        float n2 = tanhf(Gin + r2 * Ghn);
        v2 = (1.f - z2) * n2 + z2 * hvh;
    }

    __syncwarp();
#pragma unroll
    for (int i = 0; i < 4; i++) sH[i * 41 + lane] = v1[i];   // reuse sH for v
    sH[hi_node * 41 + hi_col] = v2;
    __syncwarp();

#pragma unroll
    for (int i = 0; i < 4; i++) {
        float x1 = sH[i * 41 + lane];
        float x2 = (lane < 8) ? sH[i * 41 + 32 + lane] : -FLT_MAX;
        float vmax = fmaxf(x1, x2);
#pragma unroll
        for (int o = 16; o > 0; o >>= 1)
            vmax = fmaxf(vmax, __shfl_xor_sync(0xffffffffu, vmax, o));
        float se = __expf(x1 - vmax) + ((lane < 8) ? __expf(x2 - vmax) : 0.f);
#pragma unroll
        for (int o = 16; o > 0; o >>= 1)
            se += __shfl_xor_sync(0xffffffffu, se, o);
        float ls = vmax + logf(se);

        int b = (n0 + i) * 40;
        out[b + lane] = x1 - ls;
        if (lane < 8) out[b + 32 + lane] = x2 - ls;
    }
}

// ---------------- launch ----------------
extern "C" void kernel_launch(void* const* d_in, const int* in_sizes, int n_in,
                              void* d_out, int out_size) {
    const float* x   = (const float*)d_in[0];
    const int*   ei  = (const int*)d_in[1];     // int32 (JAX x64 disabled)
    const float* ew  = (const float*)d_in[2];
    const float* W1p = (const float*)d_in[3];
    const float* W1m = (const float*)d_in[4];
    const float* g1wih = (const float*)d_in[5];
    const float* g1whh = (const float*)d_in[6];
    const float* g1bih = (const float*)d_in[7];
    const float* g1bhh = (const float*)d_in[8];
    const float* W2p = (const float*)d_in[9];
    const float* W2m = (const float*)d_in[10];
    const float* g2wih = (const float*)d_in[11];
    const float* g2whh = (const float*)d_in[12];
    const float* g2bih = (const float*)d_in[13];
    const float* g2bhh = (const float*)d_in[14];
    float* out = (float*)d_out;

    const int smem2 = (2 * 32 * 121 + 8 * 428) * 4;   // 44672 B
    cudaFuncSetAttribute(k_gru2, cudaFuncAttributeMaxDynamicSharedMemorySize, smem2);

    k_prepackA<<<17, 256>>>(W1m, g1wih, W2p, W2m);      // 3072 + 1280 entries
    k_prepackB<<<30, 256>>>(g2wih, W2p, g2whh);          // 3840 + 3840 entries

    k_proj1<<<NB128, 128>>>(x, W1p);

    long long th1 = (long long)N_EDGES * 8;
    k_edge1<<<(int)((th1 + 255) / 256), 256>>>(ei, ew);

    k_gru1_proj2<<<NB128, 128>>>(g1whh, g1bih, g1bhh, W2p);

    k_edge2<<<(int)((th1 + 255) / 256), 256>>>(ei, ew);

    k_gru2<<<NB256, 256, smem2>>>(out, g2bih, g2bhh);
}

// round 17
// speedup vs baseline: 1.3721x; 1.0915x over previous
#include <cuda_runtime.h>
#include <cstdint>
#include <float.h>

#define N_NODES 100000
#define N_EDGES 2000000
#define HID 32
#define NCLS 40
#define NB128 3125    // blocks of 128 threads, 4 warps x 8 nodes = 32 nodes/block
#define NB256 3125    // blocks of 256 threads, 8 warps x 4 nodes = 32 nodes/block

// ---------------- scratch (static device memory; no allocation) ----------------
__device__ float g_h1 [N_NODES * HID];
__device__ float g_agg1[N_NODES * HID];
__device__ float g_hr [N_NODES * HID];    // relu(gru1) — scattered for layer 2
__device__ float g_agg2[N_NODES * HID];   // raw 32-wide aggregation for layer 2

// folded weights
__device__ float g_C1[32 * 96];    // W1m @ wih1.T
__device__ float g_D [32 * 40];    // W2p @ W2m
__device__ float g_C2[32 * 120];   // W2p @ W2m @ wih2.T
__device__ float g_E2[32 * 120];   // W2p @ whh2.T

__device__ __forceinline__ void red_add_v4(float* addr, float4 v) {
    asm volatile("red.global.add.v4.f32 [%0], {%1,%2,%3,%4};"
                 :: "l"(addr), "f"(v.x), "f"(v.y), "f"(v.z), "f"(v.w)
                 : "memory");
}

// ---------------- K0a: C1 = W1m@wih1.T ; D = W2p@W2m ----------------
__global__ void k_prepackA(const float* __restrict__ W1m,
                           const float* __restrict__ wih1,
                           const float* __restrict__ W2p,
                           const float* __restrict__ W2m) {
    int idx = blockIdx.x * 256 + threadIdx.x;
    if (idx < 32 * 96) {
        int k = idx / 96, r = idx % 96;
        float s = 0.f;
#pragma unroll 8
        for (int j = 0; j < 32; j++)
            s = fmaf(W1m[k * 32 + j], wih1[r * 32 + j], s);
        g_C1[idx] = s;
    } else if (idx < 32 * 96 + 32 * 40) {
        int i2 = idx - 32 * 96;
        int k = i2 / 40, l = i2 % 40;
        float s = 0.f;
#pragma unroll 8
        for (int j = 0; j < 40; j++)
            s = fmaf(W2p[k * 40 + j], W2m[j * 40 + l], s);
        g_D[i2] = s;
    }
}

// ---------------- K0b: C2 = D@wih2.T ; E2 = W2p@whh2.T (each 32x120) ----------
__global__ void k_prepackB(const float* __restrict__ wih2,
                           const float* __restrict__ W2p,
                           const float* __restrict__ whh2) {
    int idx = blockIdx.x * 256 + threadIdx.x;
    if (idx < 32 * 120) {
        int k = idx / 120, r = idx % 120;
        float s = 0.f;
#pragma unroll 8
        for (int l = 0; l < 40; l++)
            s = fmaf(g_D[k * 40 + l], wih2[r * 40 + l], s);
        g_C2[idx] = s;
    } else if (idx < 2 * 32 * 120) {
        int i2 = idx - 32 * 120;
        int k = i2 / 120, r = i2 % 120;
        float s = 0.f;
#pragma unroll 8
        for (int j = 0; j < 40; j++)
            s = fmaf(W2p[k * 40 + j], whh2[r * 40 + j], s);
        g_E2[i2] = s;
    }
}

// ---------------- K1: h1 = x@W1p, zero agg1 (8 nodes/warp) ---------------------
__global__ void __launch_bounds__(128) k_proj1(const float* __restrict__ x,
                        const float* __restrict__ Wp) {
    __shared__ float sWp[1024];
    int t = threadIdx.x;
    for (int i = t; i < 1024; i += 128) sWp[i] = Wp[i];
    __syncthreads();

    int lane = t & 31;
    int n0 = blockIdx.x * 32 + (t >> 5) * 8;

    float xv[8], h[8];
#pragma unroll
    for (int i = 0; i < 8; i++) { xv[i] = x[(n0 + i) * 32 + lane]; h[i] = 0.f; }

#pragma unroll 8
    for (int k = 0; k < 32; k++) {
        float w = sWp[k * 32 + lane];
#pragma unroll
        for (int i = 0; i < 8; i++)
            h[i] = fmaf(__shfl_sync(0xffffffffu, xv[i], k), w, h[i]);
    }
#pragma unroll
    for (int i = 0; i < 8; i++) {
        int idx = (n0 + i) * 32 + lane;
        g_h1[idx] = h[i];
        g_agg1[idx] = 0.f;
    }
}

// ---------------- K2: edge scatter layer 1 — scatter h1 rows -------------------
__global__ void k_edge1(const int* __restrict__ ei,
                        const float* __restrict__ ew) {
    long long tid = (long long)blockIdx.x * blockDim.x + threadIdx.x;
    int e = (int)(tid >> 3);
    if (e >= N_EDGES) return;
    int q = (int)(tid & 7);
    int src = ei[e];
    int dst = ei[N_EDGES + e];
    float w = ew[e];
    const float4* hrow = (const float4*)&g_h1[src * 32];
    float4 m = hrow[q];
    m.x *= w; m.y *= w; m.z *= w; m.w *= w;
    red_add_v4(&g_agg1[dst * 32 + q * 4], m);
}

// ------- K3: GRU1 (gi = agg@C1) + ReLU -> hr, zero agg2 (8 nodes/warp) ---------
__global__ void __launch_bounds__(128) k_gru1(
                             const float* __restrict__ whh,
                             const float* __restrict__ bih,
                             const float* __restrict__ bhh) {
    __shared__ float sWi[32 * 97]; // C1 [k][r], padded
    __shared__ float sWh[32 * 97]; // whh transposed [k][r], padded
    int t = threadIdx.x;
    for (int i = t; i < 96 * 32; i += 128) {
        int k = i / 96, r = i % 96;
        sWi[k * 97 + r] = g_C1[i];
    }
    for (int i = t; i < 96 * 32; i += 128) {
        int r = i >> 5, k = i & 31;       // whh row-major [96][32] -> [k][r]
        sWh[k * 97 + r] = whh[i];
    }
    __syncthreads();

    int lane = t & 31;
    int n0 = blockIdx.x * 32 + (t >> 5) * 8;

    float a[8], hv[8];
    float gir[8], giz[8], gin[8], ghr[8], ghz[8], ghn[8];
    {
        float b_ir = bih[lane], b_iz = bih[32 + lane], b_in = bih[64 + lane];
        float b_hr = bhh[lane], b_hz = bhh[32 + lane], b_hn = bhh[64 + lane];
#pragma unroll
        for (int i = 0; i < 8; i++) {
            int idx = (n0 + i) * 32 + lane;
            a[i] = g_agg1[idx];
            hv[i] = g_h1[idx];
            gir[i] = b_ir; giz[i] = b_iz; gin[i] = b_in;
            ghr[i] = b_hr; ghz[i] = b_hz; ghn[i] = b_hn;
        }
    }

#pragma unroll 4
    for (int k = 0; k < 32; k++) {
        const float* wi = &sWi[k * 97];
        const float* wh = &sWh[k * 97];
        float wir = wi[lane], wiz = wi[32 + lane], win = wi[64 + lane];
        float whr = wh[lane], whz = wh[32 + lane], whn = wh[64 + lane];
#pragma unroll
        for (int i = 0; i < 8; i++) {
            float ak = __shfl_sync(0xffffffffu, a[i],  k);
            float hk = __shfl_sync(0xffffffffu, hv[i], k);
            gir[i] = fmaf(ak, wir, gir[i]);
            giz[i] = fmaf(ak, wiz, giz[i]);
            gin[i] = fmaf(ak, win, gin[i]);
            ghr[i] = fmaf(hk, whr, ghr[i]);
            ghz[i] = fmaf(hk, whz, ghz[i]);
            ghn[i] = fmaf(hk, whn, ghn[i]);
        }
    }

#pragma unroll
    for (int i = 0; i < 8; i++) {
        float r = 1.f / (1.f + __expf(-(gir[i] + ghr[i])));
        float z = 1.f / (1.f + __expf(-(giz[i] + ghz[i])));
        float n = tanhf(gin[i] + r * ghn[i]);
        float hrv = fmaxf((1.f - z) * n + z * hv[i], 0.f);
        int idx = (n0 + i) * 32 + lane;
        g_hr[idx] = hrv;
        g_agg2[idx] = 0.f;
    }
}

// ---------------- K4: edge scatter layer 2 — scatter hr rows (32-wide) ---------
__global__ void k_edge2(const int* __restrict__ ei,
                        const float* __restrict__ ew) {
    long long tid = (long long)blockIdx.x * blockDim.x + threadIdx.x;
    int e = (int)(tid >> 3);
    if (e >= N_EDGES) return;
    int q = (int)(tid & 7);
    int src = ei[e];
    int dst = ei[N_EDGES + e];
    float w = ew[e];
    const float4* hrow = (const float4*)&g_hr[src * 32];
    float4 m = hrow[q];
    m.x *= w; m.y *= w; m.z *= w; m.w *= w;
    red_add_v4(&g_agg2[dst * 32 + q * 4], m);
}

// -- K5: GRU2 (gi=agg@C2, gh=hr@E2, h2=hr@W2p in-loop) + log_softmax ------------
__global__ void __launch_bounds__(256) k_gru2(float* __restrict__ out,
                       const float* __restrict__ W2p,
                       const float* __restrict__ bih,
                       const float* __restrict__ bhh) {
    extern __shared__ float dyn[];
    float* sWi = dyn;                  // C2 [k][r], k<32, padded stride 121
    float* sWe = sWi + 32 * 121;       // E2 [k][r], k<32, padded stride 121
    float* sWp = sWe + 32 * 121;       // W2p [k][c], 32x40
    float* sStage = sWp + 32 * 40;     // 8 warps * (132 + 132 + 164)

    int t = threadIdx.x;
    for (int i = t; i < 32 * 120; i += 256) {
        int k = i / 120, r = i % 120;
        sWi[k * 121 + r] = g_C2[i];
        sWe[k * 121 + r] = g_E2[i];
    }
    for (int i = t; i < 32 * 40; i += 256) sWp[i] = W2p[i];
    __syncthreads();

    int lane = t & 31;
    int warp = t >> 5;
    int n0 = blockIdx.x * 32 + warp * 4;
    float* sA = sStage + warp * 428;   // 4*33 agg (32-wide)
    float* sR = sA + 132;              // 4*33 hr  (32-wide)
    float* sV = sR + 132;              // 4*41 v   (softmax staging)

    float a_lo[4], r_lo[4];
#pragma unroll
    for (int i = 0; i < 4; i++) {
        int b32 = (n0 + i) * 32;
        float av = g_agg2[b32 + lane];
        float rv = g_hr[b32 + lane];
        a_lo[i] = av; r_lo[i] = rv;
        sA[i * 33 + lane] = av;
        sR[i * 33 + lane] = rv;
    }
    __syncwarp();

    float gir[4], giz[4], gin[4], ghr[4], ghz[4], ghn[4];
    float h2lo[4];
    {
        float b0 = bih[lane], b1 = bih[40 + lane], b2 = bih[80 + lane];
        float b3 = bhh[lane], b4 = bhh[40 + lane], b5 = bhh[80 + lane];
#pragma unroll
        for (int i = 0; i < 4; i++) {
            gir[i] = b0; giz[i] = b1; gin[i] = b2;
            ghr[i] = b3; ghz[i] = b4; ghn[i] = b5;
            h2lo[i] = 0.f;
        }
    }
    int hi_node = lane >> 3;
    int hi_col  = 32 + (lane & 7);
    float Gir = bih[hi_col], Giz = bih[40 + hi_col], Gin = bih[80 + hi_col];
    float Ghr = bhh[hi_col], Ghz = bhh[40 + hi_col], Ghn = bhh[80 + hi_col];
    float h2hi = 0.f;
    const float* aN = sA + hi_node * 33;
    const float* rN = sR + hi_node * 33;

#pragma unroll 4
    for (int k = 0; k < 32; k++) {
        const float* wi = &sWi[k * 121];
        const float* we = &sWe[k * 121];
        const float* wp = &sWp[k * 40];
        float wi0 = wi[lane], wi1 = wi[40 + lane], wi2 = wi[80 + lane];
        float we0 = we[lane], we1 = we[40 + lane], we2 = we[80 + lane];
        float wp0 = wp[lane];
        {
            float ak = aN[k], rk = rN[k];
            Gir = fmaf(ak, wi[hi_col],      Gir);
            Giz = fmaf(ak, wi[40 + hi_col], Giz);
            Gin = fmaf(ak, wi[80 + hi_col], Gin);
            Ghr = fmaf(rk, we[hi_col],      Ghr);
            Ghz = fmaf(rk, we[40 + hi_col], Ghz);
            Ghn = fmaf(rk, we[80 + hi_col], Ghn);
            h2hi = fmaf(rk, wp[hi_col],     h2hi);
        }
#pragma unroll
        for (int i = 0; i < 4; i++) {
            float ak = __shfl_sync(0xffffffffu, a_lo[i], k);
            float rk = __shfl_sync(0xffffffffu, r_lo[i], k);
            gir[i] = fmaf(ak, wi0, gir[i]);
            giz[i] = fmaf(ak, wi1, giz[i]);
            gin[i] = fmaf(ak, wi2, gin[i]);
            ghr[i] = fmaf(rk, we0, ghr[i]);
            ghz[i] = fmaf(rk, we1, ghz[i]);
            ghn[i] = fmaf(rk, we2, ghn[i]);
            h2lo[i] = fmaf(rk, wp0, h2lo[i]);
        }
    }

    float v1[4];
#pragma unroll
    for (int i = 0; i < 4; i++) {
        float r1 = 1.f / (1.f + __expf(-(gir[i] + ghr[i])));
        float z1 = 1.f / (1.f + __expf(-(giz[i] + ghz[i])));
        float n1 = tanhf(gin[i] + r1 * ghn[i]);
        v1[i] = (1.f - z1) * n1 + z1 * h2lo[i];
    }
    float v2;
    {
        float r2 = 1.f / (1.f + __expf(-(Gir + Ghr)));
        float z2 = 1.f / (1.f + __expf(-(Giz + Ghz)));
        float n2 = tanhf(Gin + r2 * Ghn);
        v2 = (1.f - z2) * n2 + z2 * h2hi;
    }

    __syncwarp();
#pragma unroll
    for (int i = 0; i < 4; i++) sV[i * 41 + lane] = v1[i];
    sV[hi_node * 41 + hi_col] = v2;
    __syncwarp();

#pragma unroll
    for (int i = 0; i < 4; i++) {
        float x1 = sV[i * 41 + lane];
        float x2 = (lane < 8) ? sV[i * 41 + 32 + lane] : -FLT_MAX;
        float vmax = fmaxf(x1, x2);
#pragma unroll
        for (int o = 16; o > 0; o >>= 1)
            vmax = fmaxf(vmax, __shfl_xor_sync(0xffffffffu, vmax, o));
        float se = __expf(x1 - vmax) + ((lane < 8) ? __expf(x2 - vmax) : 0.f);
#pragma unroll
        for (int o = 16; o > 0; o >>= 1)
            se += __shfl_xor_sync(0xffffffffu, se, o);
        float ls = vmax + logf(se);

        int b = (n0 + i) * 40;
        out[b + lane] = x1 - ls;
        if (lane < 8) out[b + 32 + lane] = x2 - ls;
    }
}

// ---------------- launch ----------------
extern "C" void kernel_launch(void* const* d_in, const int* in_sizes, int n_in,
                              void* d_out, int out_size) {
    const float* x   = (const float*)d_in[0];
    const int*   ei  = (const int*)d_in[1];     // int32 (JAX x64 disabled)
    const float* ew  = (const float*)d_in[2];
    const float* W1p = (const float*)d_in[3];
    const float* W1m = (const float*)d_in[4];
    const float* g1wih = (const float*)d_in[5];
    const float* g1whh = (const float*)d_in[6];
    const float* g1bih = (const float*)d_in[7];
    const float* g1bhh = (const float*)d_in[8];
    const float* W2p = (const float*)d_in[9];
    const float* W2m = (const float*)d_in[10];
    const float* g2wih = (const float*)d_in[11];
    const float* g2whh = (const float*)d_in[12];
    const float* g2bih = (const float*)d_in[13];
    const float* g2bhh = (const float*)d_in[14];
    float* out = (float*)d_out;

    const int smem2 = (2 * 32 * 121 + 32 * 40 + 8 * 428) * 4;   // 49792 B
    cudaFuncSetAttribute(k_gru2, cudaFuncAttributeMaxDynamicSharedMemorySize, smem2);

    k_prepackA<<<17, 256>>>(W1m, g1wih, W2p, W2m);      // 3072 + 1280 entries
    k_prepackB<<<30, 256>>>(g2wih, W2p, g2whh);          // 3840 + 3840 entries

    k_proj1<<<NB128, 128>>>(x, W1p);

    long long th1 = (long long)N_EDGES * 8;
    k_edge1<<<(int)((th1 + 255) / 256), 256>>>(ei, ew);

    k_gru1<<<NB128, 128>>>(g1whh, g1bih, g1bhh);

    k_edge2<<<(int)((th1 + 255) / 256), 256>>>(ei, ew);

    k_gru2<<<NB256, 256, smem2>>>(out, W2p, g2bih, g2bhh);
}